// round 2
// baseline (speedup 1.0000x reference)
#include <cuda_runtime.h>
#include <math.h>

// ---------------- problem constants ----------------
#define B_ 2
#define T_ 1024
#define C_ 1024
#define H_ 16
#define HD_ 64
#define L_ 12
#define V_ 50257
#define MTOT (B_ * T_)      // 2048 token rows
#define FF_ (4 * C_)        // 4096

// ---------------- static device scratch (no allocations allowed) ----------------
__device__ float g_x[MTOT * C_];
__device__ float g_h[MTOT * C_];
__device__ float g_q[MTOT * C_];
__device__ float g_k[MTOT * C_];
__device__ float g_v[MTOT * C_];
__device__ float g_y[MTOT * C_];
__device__ float g_mlp[MTOT * FF_];
__device__ float g_att[(size_t)B_ * H_ * T_ * T_];   // 128 MB
__device__ float g_nll[MTOT];
__device__ float g_logits[(size_t)MTOT * V_];        // fallback if d_out can't hold logits

// ---------------- helpers ----------------
__device__ __forceinline__ float gelu_exact(float v) {
    return 0.5f * v * (1.0f + erff(v * 0.7071067811865476f));
}

// ---------------- embedding ----------------
__global__ void embed_kernel(const int* __restrict__ idx,
                             const float* __restrict__ tok,
                             const float* __restrict__ pos,
                             float* __restrict__ x) {
    int row = blockIdx.x;            // 0..MTOT-1
    int t = row % T_;
    int id = idx[row];
    const float* tr = tok + (size_t)id * C_;
    const float* pr = pos + (size_t)t * C_;
    float* xr = x + (size_t)row * C_;
#pragma unroll
    for (int j = 0; j < 4; j++) {
        int c = threadIdx.x + j * 256;
        xr[c] = tr[c] + pr[c];
    }
}

// ---------------- layernorm (one block per row, C=1024) ----------------
__global__ void layernorm_kernel(const float* __restrict__ x,
                                 const float* __restrict__ w,
                                 const float* __restrict__ b,
                                 float* __restrict__ out) {
    int row = blockIdx.x;
    int tid = threadIdx.x;
    const float* xr = x + (size_t)row * C_;
    float v[4];
    float s = 0.f;
#pragma unroll
    for (int j = 0; j < 4; j++) { v[j] = xr[tid + j * 256]; s += v[j]; }
    __shared__ float red[256];
    red[tid] = s; __syncthreads();
    for (int off = 128; off > 0; off >>= 1) {
        if (tid < off) red[tid] += red[tid + off];
        __syncthreads();
    }
    float mu = red[0] * (1.0f / C_);
    __syncthreads();
    float s2 = 0.f;
#pragma unroll
    for (int j = 0; j < 4; j++) { float d = v[j] - mu; s2 += d * d; }
    red[tid] = s2; __syncthreads();
    for (int off = 128; off > 0; off >>= 1) {
        if (tid < off) red[tid] += red[tid + off];
        __syncthreads();
    }
    float var = red[0] * (1.0f / C_);
    float rstd = rsqrtf(var + 1e-5f);
    float* orow = out + (size_t)row * C_;
#pragma unroll
    for (int j = 0; j < 4; j++) {
        int c = tid + j * 256;
        orow[c] = (v[j] - mu) * rstd * w[c] + b[c];
    }
}

// ---------------- generic SGEMM: C = act(A@B + bias) (+resid) ----------------
// A[M,K] lda, B[K,N] ldb row-major. 128x128 tile, BK=16, 256 threads, 8x8/thread.
#define GBM 128
#define GBN 128
#define GBK 16

template <int ACT, bool HAS_BIAS, bool HAS_RES>
__global__ void __launch_bounds__(256, 2)
gemm_nn_kernel(const float* __restrict__ A, int lda,
               const float* __restrict__ Bm, int ldb,
               const float* __restrict__ bias,
               const float* __restrict__ resid, int ldr,
               float* __restrict__ Cm, int ldc,
               int M, int N, int K) {
    __shared__ float As[GBK][GBM];
    __shared__ float Bs[GBK][GBN];
    int tid = threadIdx.x;
    int tx = tid & 15, ty = tid >> 4;
    int rowBase = blockIdx.y * GBM;
    int colBase = blockIdx.x * GBN;

    float acc[8][8] = {};
    for (int kt = 0; kt < K; kt += GBK) {
#pragma unroll
        for (int i = 0; i < 8; i++) {
            int idx = tid + i * 256;           // 2048 elems
            int m = idx >> 4, kk = idx & 15;
            int gr = rowBase + m, gc = kt + kk;
            As[kk][m] = (gr < M && gc < K) ? A[(size_t)gr * lda + gc] : 0.f;
        }
#pragma unroll
        for (int i = 0; i < 8; i++) {
            int idx = tid + i * 256;
            int kk = idx >> 7, n = idx & 127;
            int gr = kt + kk, gc = colBase + n;
            Bs[kk][n] = (gr < K && gc < N) ? Bm[(size_t)gr * ldb + gc] : 0.f;
        }
        __syncthreads();
#pragma unroll
        for (int kk = 0; kk < GBK; kk++) {
            float a[8], b[8];
#pragma unroll
            for (int i = 0; i < 8; i++) a[i] = As[kk][ty * 8 + i];
#pragma unroll
            for (int j = 0; j < 8; j++) b[j] = Bs[kk][tx * 8 + j];
#pragma unroll
            for (int i = 0; i < 8; i++)
#pragma unroll
                for (int j = 0; j < 8; j++)
                    acc[i][j] = fmaf(a[i], b[j], acc[i][j]);
        }
        __syncthreads();
    }
#pragma unroll
    for (int i = 0; i < 8; i++) {
        int gr = rowBase + ty * 8 + i;
        if (gr >= M) continue;
#pragma unroll
        for (int j = 0; j < 8; j++) {
            int gc = colBase + tx * 8 + j;
            if (gc >= N) continue;
            float v = acc[i][j];
            if (HAS_BIAS) v += bias[gc];
            if (ACT == 1) v = gelu_exact(v);
            if (HAS_RES) v += resid[(size_t)gr * ldr + gc];
            Cm[(size_t)gr * ldc + gc] = v;
        }
    }
}

// ---------------- attention scores: att[bh,q,k] = (Q.K^T)*scale, causal mask ----------------
// grid (T/64, T/64, B*H), 256 threads, 4x4/thread, full HD=64 slab in smem.
__global__ void attn_scores_kernel(const float* __restrict__ q,
                                   const float* __restrict__ k,
                                   float* __restrict__ att) {
    int z = blockIdx.z;
    int b = z / H_, h = z % H_;
    int rowBase = blockIdx.y * 64;
    int colBase = blockIdx.x * 64;
    int tid = threadIdx.x, tx = tid & 15, ty = tid >> 4;
    float* ab = att + (size_t)z * T_ * T_;

    if (colBase > rowBase + 63) {   // fully above diagonal: masked
#pragma unroll
        for (int i = 0; i < 4; i++) {
            int gr = rowBase + ty * 4 + i;
#pragma unroll
            for (int j = 0; j < 4; j++)
                ab[(size_t)gr * T_ + colBase + tx * 4 + j] = -1e30f;
        }
        return;
    }
    const float* qb = q + (size_t)b * T_ * C_ + h * HD_;
    const float* kb = k + (size_t)b * T_ * C_ + h * HD_;
    __shared__ float Qs[HD_][65];
    __shared__ float Ks[HD_][65];
#pragma unroll
    for (int i = 0; i < 16; i++) {
        int idx = tid + i * 256;       // 4096 = 64 rows x 64 dims
        int m = idx >> 6, d = idx & 63;
        Qs[d][m] = qb[(size_t)(rowBase + m) * C_ + d];
        Ks[d][m] = kb[(size_t)(colBase + m) * C_ + d];
    }
    __syncthreads();
    float acc[4][4] = {};
#pragma unroll
    for (int d = 0; d < HD_; d++) {
        float a[4], bb[4];
#pragma unroll
        for (int i = 0; i < 4; i++) a[i] = Qs[d][ty * 4 + i];
#pragma unroll
        for (int j = 0; j < 4; j++) bb[j] = Ks[d][tx * 4 + j];
#pragma unroll
        for (int i = 0; i < 4; i++)
#pragma unroll
            for (int j = 0; j < 4; j++)
                acc[i][j] = fmaf(a[i], bb[j], acc[i][j]);
    }
    const float scale = 0.125f;  // 1/sqrt(64)
#pragma unroll
    for (int i = 0; i < 4; i++) {
        int gr = rowBase + ty * 4 + i;
#pragma unroll
        for (int j = 0; j < 4; j++) {
            int gc = colBase + tx * 4 + j;
            ab[(size_t)gr * T_ + gc] = (gc <= gr) ? acc[i][j] * scale : -1e30f;
        }
    }
}

// ---------------- row softmax over T, one block per (b,h,q) row ----------------
__global__ void softmax_kernel(float* __restrict__ att) {
    float* p = att + (size_t)blockIdx.x * T_;
    int tid = threadIdx.x;
    float v[4];
    float m = -INFINITY;
#pragma unroll
    for (int j = 0; j < 4; j++) { v[j] = p[tid + j * 256]; m = fmaxf(m, v[j]); }
    __shared__ float red[256];
    red[tid] = m; __syncthreads();
    for (int off = 128; off > 0; off >>= 1) {
        if (tid < off) red[tid] = fmaxf(red[tid], red[tid + off]);
        __syncthreads();
    }
    m = red[0]; __syncthreads();
    float s = 0.f;
#pragma unroll
    for (int j = 0; j < 4; j++) { v[j] = expf(v[j] - m); s += v[j]; }
    red[tid] = s; __syncthreads();
    for (int off = 128; off > 0; off >>= 1) {
        if (tid < off) red[tid] += red[tid + off];
        __syncthreads();
    }
    float inv = 1.0f / red[0];
#pragma unroll
    for (int j = 0; j < 4; j++) p[tid + j * 256] = v[j] * inv;
}

// ---------------- y = att @ V (per head, causal k-bound) ----------------
// grid (T/64, B*H), 256 threads, 4x4/thread, BK=16
__global__ void attn_av_kernel(const float* __restrict__ att,
                               const float* __restrict__ v,
                               float* __restrict__ y) {
    int z = blockIdx.y;
    int b = z / H_, h = z % H_;
    const float* ab = att + (size_t)z * T_ * T_;
    const float* vb = v + (size_t)b * T_ * C_ + h * HD_;
    float* yb = y + (size_t)b * T_ * C_ + h * HD_;
    int rowBase = blockIdx.x * 64;
    int tid = threadIdx.x, tx = tid & 15, ty = tid >> 4;

    __shared__ float As[16][65];
    __shared__ float Bs[16][65];
    float acc[4][4] = {};
    int kend = rowBase + 64;          // causal: att[q,k]=0 for k>q
    if (kend > T_) kend = T_;
    for (int kt = 0; kt < kend; kt += 16) {
#pragma unroll
        for (int i = 0; i < 4; i++) {
            int idx = tid + i * 256;   // 1024 = 64 x 16
            int m = idx >> 4, kk = idx & 15;
            As[kk][m] = ab[(size_t)(rowBase + m) * T_ + kt + kk];
        }
#pragma unroll
        for (int i = 0; i < 4; i++) {
            int idx = tid + i * 256;   // 1024 = 16 x 64
            int kk = idx >> 6, n = idx & 63;
            Bs[kk][n] = vb[(size_t)(kt + kk) * C_ + n];
        }
        __syncthreads();
#pragma unroll
        for (int kk = 0; kk < 16; kk++) {
            float a[4], bb[4];
#pragma unroll
            for (int i = 0; i < 4; i++) a[i] = As[kk][ty * 4 + i];
#pragma unroll
            for (int j = 0; j < 4; j++) bb[j] = Bs[kk][tx * 4 + j];
#pragma unroll
            for (int i = 0; i < 4; i++)
#pragma unroll
                for (int j = 0; j < 4; j++)
                    acc[i][j] = fmaf(a[i], bb[j], acc[i][j]);
        }
        __syncthreads();
    }
#pragma unroll
    for (int i = 0; i < 4; i++) {
        int gr = rowBase + ty * 4 + i;
#pragma unroll
        for (int j = 0; j < 4; j++)
            yb[(size_t)gr * C_ + tx * 4 + j] = acc[i][j];
    }
}

// ---------------- per-row NLL over V=50257 (two passes) ----------------
__global__ void nll_kernel(const float* __restrict__ logits,
                           const int* __restrict__ targets,
                           float* __restrict__ nll) {
    int row = blockIdx.x;
    const float* p = logits + (size_t)row * V_;
    int tid = threadIdx.x;
    __shared__ float red[256];
    float m = -INFINITY;
    for (int c = tid; c < V_; c += 256) m = fmaxf(m, p[c]);
    red[tid] = m; __syncthreads();
    for (int off = 128; off > 0; off >>= 1) {
        if (tid < off) red[tid] = fmaxf(red[tid], red[tid + off]);
        __syncthreads();
    }
    m = red[0]; __syncthreads();
    float s = 0.f;
    for (int c = tid; c < V_; c += 256) s += expf(p[c] - m);
    red[tid] = s; __syncthreads();
    for (int off = 128; off > 0; off >>= 1) {
        if (tid < off) red[tid] += red[tid + off];
        __syncthreads();
    }
    if (tid == 0) {
        float lt = p[targets[row]];
        nll[row] = -(lt - m - logf(red[0]));
    }
}

__global__ void loss_kernel(const float* __restrict__ nll, float* __restrict__ out) {
    __shared__ float red[256];
    int tid = threadIdx.x;
    float s = 0.f;
    for (int c = tid; c < MTOT; c += 256) s += nll[c];
    red[tid] = s; __syncthreads();
    for (int off = 128; off > 0; off >>= 1) {
        if (tid < off) red[tid] += red[tid + off];
        __syncthreads();
    }
    if (tid == 0) out[0] = red[0] * (1.0f / MTOT);
}

// ---------------- host launcher ----------------
extern "C" void kernel_launch(void* const* d_in, const int* in_sizes, int n_in,
                              void* d_out, int out_size) {
    const int*   idx     = (const int*)d_in[0];
    const int*   targets = (const int*)d_in[1];
    const float* tok     = (const float*)d_in[2];
    const float* pos     = (const float*)d_in[3];
    const float* ln1w    = (const float*)d_in[4];
    const float* ln1b    = (const float*)d_in[5];
    const float* ln2w    = (const float*)d_in[6];
    const float* ln2b    = (const float*)d_in[7];
    const float* Wq      = (const float*)d_in[8];
    const float* bq      = (const float*)d_in[9];
    const float* Wk      = (const float*)d_in[10];
    const float* bk      = (const float*)d_in[11];
    const float* Wv      = (const float*)d_in[12];
    const float* bv      = (const float*)d_in[13];
    const float* Wo      = (const float*)d_in[14];
    const float* bo      = (const float*)d_in[15];
    const float* W1      = (const float*)d_in[16];
    const float* b1      = (const float*)d_in[17];
    const float* W2      = (const float*)d_in[18];
    const float* b2      = (const float*)d_in[19];
    const float* lnfw    = (const float*)d_in[20];
    const float* lnfb    = (const float*)d_in[21];
    const float* headw   = (const float*)d_in[22];
    float* out = (float*)d_out;

    float *x, *h, *q, *k, *v, *y, *mlp, *att, *nllbuf, *lgs;
    cudaGetSymbolAddress((void**)&x, g_x);
    cudaGetSymbolAddress((void**)&h, g_h);
    cudaGetSymbolAddress((void**)&q, g_q);
    cudaGetSymbolAddress((void**)&k, g_k);
    cudaGetSymbolAddress((void**)&v, g_v);
    cudaGetSymbolAddress((void**)&y, g_y);
    cudaGetSymbolAddress((void**)&mlp, g_mlp);
    cudaGetSymbolAddress((void**)&att, g_att);
    cudaGetSymbolAddress((void**)&nllbuf, g_nll);
    cudaGetSymbolAddress((void**)&lgs, g_logits);

    const size_t BTV = (size_t)MTOT * V_;
    float* logits = ((size_t)out_size >= BTV) ? out : lgs;

    embed_kernel<<<MTOT, 256>>>(idx, tok, pos, x);

    dim3 gC((C_ + GBN - 1) / GBN, (MTOT + GBM - 1) / GBM);     // N=1024 GEMMs
    dim3 gF((FF_ + GBN - 1) / GBN, (MTOT + GBM - 1) / GBM);    // N=4096 GEMM
    dim3 gH((V_ + GBN - 1) / GBN, (MTOT + GBM - 1) / GBM);     // head GEMM

    for (int l = 0; l < L_; l++) {
        const size_t oC = (size_t)l * C_;
        const size_t oCC = (size_t)l * C_ * C_;
        const size_t oCF = (size_t)l * C_ * FF_;

        layernorm_kernel<<<MTOT, 256>>>(x, ln1w + oC, ln1b + oC, h);

        gemm_nn_kernel<0, true, false><<<gC, 256>>>(h, C_, Wq + oCC, C_, bq + oC,
                                                    nullptr, 0, q, C_, MTOT, C_, C_);
        gemm_nn_kernel<0, true, false><<<gC, 256>>>(h, C_, Wk + oCC, C_, bk + oC,
                                                    nullptr, 0, k, C_, MTOT, C_, C_);
        gemm_nn_kernel<0, true, false><<<gC, 256>>>(h, C_, Wv + oCC, C_, bv + oC,
                                                    nullptr, 0, v, C_, MTOT, C_, C_);

        attn_scores_kernel<<<dim3(T_ / 64, T_ / 64, B_ * H_), 256>>>(q, k, att);
        softmax_kernel<<<B_ * H_ * T_, 256>>>(att);
        attn_av_kernel<<<dim3(T_ / 64, B_ * H_), 256>>>(att, v, y);

        gemm_nn_kernel<0, true, true><<<gC, 256>>>(y, C_, Wo + oCC, C_, bo + oC,
                                                   x, C_, x, C_, MTOT, C_, C_);

        layernorm_kernel<<<MTOT, 256>>>(x, ln2w + oC, ln2b + oC, h);

        gemm_nn_kernel<1, true, false><<<gF, 256>>>(h, C_, W1 + oCF, FF_, b1 + (size_t)l * FF_,
                                                    nullptr, 0, mlp, FF_, MTOT, FF_, C_);
        gemm_nn_kernel<0, true, true><<<gC, 256>>>(mlp, FF_, W2 + oCF, C_, b2 + oC,
                                                   x, C_, x, C_, MTOT, C_, FF_);
    }

    layernorm_kernel<<<MTOT, 256>>>(x, lnfw, lnfb, h);
    gemm_nn_kernel<0, false, false><<<gH, 256>>>(h, C_, headw, V_, nullptr,
                                                 nullptr, 0, logits, V_, MTOT, V_, C_);

    nll_kernel<<<MTOT, 256>>>(logits, targets, nllbuf);
    if ((size_t)out_size == BTV + 1) {
        loss_kernel<<<1, 256>>>(nllbuf, out + BTV);
    } else if ((size_t)out_size < BTV && out_size >= 1) {
        loss_kernel<<<1, 256>>>(nllbuf, out);
    }
}

// round 3
// speedup vs baseline: 3.9081x; 3.9081x over previous
#include <cuda_runtime.h>
#include <math.h>
#include <stdint.h>

// ---------------- problem constants ----------------
#define B_ 2
#define T_ 1024
#define C_ 1024
#define H_ 16
#define HD_ 64
#define L_ 12
#define V_ 50257
#define MTOT (B_ * T_)      // 2048 token rows
#define FF_ (4 * C_)        // 4096

// ---------------- static device scratch ----------------
__device__ float g_x[MTOT * C_];
__device__ float g_h[MTOT * C_];
__device__ float g_q[MTOT * C_];
__device__ float g_k[MTOT * C_];
__device__ float g_v[MTOT * C_];
__device__ float g_y[MTOT * C_];
__device__ float g_mlp[MTOT * FF_];
__device__ float g_att[(size_t)B_ * H_ * T_ * T_];   // 128 MB
__device__ float g_nll[MTOT];
__device__ float g_logits[(size_t)MTOT * V_];        // fallback if d_out can't hold logits

// ---------------- helpers ----------------
__device__ __forceinline__ float gelu_exact(float v) {
    return 0.5f * v * (1.0f + erff(v * 0.7071067811865476f));
}

__device__ __forceinline__ uint32_t f2tf32(float x) {
    uint32_t r;
    asm("cvt.rna.tf32.f32 %0, %1;" : "=r"(r) : "f"(x));
    return r;
}

// ---------------- embedding ----------------
__global__ void embed_kernel(const int* __restrict__ idx,
                             const float* __restrict__ tok,
                             const float* __restrict__ pos,
                             float* __restrict__ x) {
    int row = blockIdx.x;
    int t = row % T_;
    int id = idx[row];
    const float* tr = tok + (size_t)id * C_;
    const float* pr = pos + (size_t)t * C_;
    float* xr = x + (size_t)row * C_;
#pragma unroll
    for (int j = 0; j < 4; j++) {
        int c = threadIdx.x + j * 256;
        xr[c] = tr[c] + pr[c];
    }
}

// ---------------- layernorm ----------------
__global__ void layernorm_kernel(const float* __restrict__ x,
                                 const float* __restrict__ w,
                                 const float* __restrict__ b,
                                 float* __restrict__ out) {
    int row = blockIdx.x;
    int tid = threadIdx.x;
    const float* xr = x + (size_t)row * C_;
    float v[4];
    float s = 0.f;
#pragma unroll
    for (int j = 0; j < 4; j++) { v[j] = xr[tid + j * 256]; s += v[j]; }
    __shared__ float red[256];
    red[tid] = s; __syncthreads();
    for (int off = 128; off > 0; off >>= 1) {
        if (tid < off) red[tid] += red[tid + off];
        __syncthreads();
    }
    float mu = red[0] * (1.0f / C_);
    __syncthreads();
    float s2 = 0.f;
#pragma unroll
    for (int j = 0; j < 4; j++) { float d = v[j] - mu; s2 += d * d; }
    red[tid] = s2; __syncthreads();
    for (int off = 128; off > 0; off >>= 1) {
        if (tid < off) red[tid] += red[tid + off];
        __syncthreads();
    }
    float var = red[0] * (1.0f / C_);
    float rstd = rsqrtf(var + 1e-5f);
    float* orow = out + (size_t)row * C_;
#pragma unroll
    for (int j = 0; j < 4; j++) {
        int c = tid + j * 256;
        orow[c] = (v[j] - mu) * rstd * w[c] + b[c];
    }
}

// ---------------- TF32 tensor-core GEMM body ----------------
// C[M,N] = act(A[M,K] @ B[K,N] + bias) (+resid). Block tile 128x128, BK=16.
// 256 threads = 8 warps in 2(m) x 4(n); warp tile 64x32; mma m16n8k8 tf32.
// Requires: M % 128 == 0, K % 16 == 0. N arbitrary (guards on B load + C store).
template <int ACT, bool HAS_BIAS, bool HAS_RES>
__device__ __forceinline__ void gemm_body(const float* __restrict__ A, int lda,
                                          const float* __restrict__ Bm, int ldb,
                                          const float* __restrict__ bias,
                                          const float* __restrict__ resid, int ldr,
                                          float* __restrict__ Cm, int ldc,
                                          int M, int N, int K) {
    __shared__ uint32_t As[128 * 20];   // [m][k], stride 20 (conflict-free frag reads)
    __shared__ uint32_t Bs[16 * 136];   // [k][n], stride 136 (conflict-free frag reads)

    const int tid = threadIdx.x;
    const int lane = tid & 31, warp = tid >> 5;
    const int g = lane >> 2, tg = lane & 3;          // groupID, thread-in-group
    const int wm = warp >> 2, wn = warp & 3;         // 2 x 4 warp grid
    const int rowBase = blockIdx.y * 128;
    const int colBase = blockIdx.x * 128;

    float c[4][4][4];
#pragma unroll
    for (int i = 0; i < 4; i++)
#pragma unroll
        for (int j = 0; j < 4; j++)
#pragma unroll
            for (int r = 0; r < 4; r++) c[i][j][r] = 0.f;

    const bool vecB = ((ldb & 3) == 0) && (colBase + 128 <= N);

    for (int kt = 0; kt < K; kt += 16) {
        // ---- load A tile 128x16 (vectorized, always in-bounds) ----
#pragma unroll
        for (int i = 0; i < 2; i++) {
            int lin = tid + i * 256;
            int r = lin >> 2, c4 = lin & 3;
            const float4 av = *reinterpret_cast<const float4*>(
                A + (size_t)(rowBase + r) * lda + kt + c4 * 4);
            uint4 tv;
            tv.x = f2tf32(av.x); tv.y = f2tf32(av.y);
            tv.z = f2tf32(av.z); tv.w = f2tf32(av.w);
            *reinterpret_cast<uint4*>(&As[r * 20 + c4 * 4]) = tv;
        }
        // ---- load B tile 16x128 ----
        if (vecB) {
#pragma unroll
            for (int i = 0; i < 2; i++) {
                int lin = tid + i * 256;
                int r = lin >> 5, c4 = lin & 31;
                const float4 bv = *reinterpret_cast<const float4*>(
                    Bm + (size_t)(kt + r) * ldb + colBase + c4 * 4);
                uint4 tv;
                tv.x = f2tf32(bv.x); tv.y = f2tf32(bv.y);
                tv.z = f2tf32(bv.z); tv.w = f2tf32(bv.w);
                *reinterpret_cast<uint4*>(&Bs[r * 136 + c4 * 4]) = tv;
            }
        } else {
#pragma unroll
            for (int i = 0; i < 8; i++) {
                int lin = tid + i * 256;
                int r = lin >> 7, cc = lin & 127;
                int gc = colBase + cc;
                float vv = (gc < N) ? Bm[(size_t)(kt + r) * ldb + gc] : 0.f;
                Bs[r * 136 + cc] = f2tf32(vv);
            }
        }
        __syncthreads();

#pragma unroll
        for (int k8 = 0; k8 < 16; k8 += 8) {
            uint32_t af[4][4], bf[4][2];
#pragma unroll
            for (int mt = 0; mt < 4; mt++) {
                int mrow = wm * 64 + mt * 16 + g;
                af[mt][0] = As[mrow * 20 + k8 + tg];
                af[mt][1] = As[(mrow + 8) * 20 + k8 + tg];
                af[mt][2] = As[mrow * 20 + k8 + tg + 4];
                af[mt][3] = As[(mrow + 8) * 20 + k8 + tg + 4];
            }
#pragma unroll
            for (int nt = 0; nt < 4; nt++) {
                int ncol = wn * 32 + nt * 8 + g;
                bf[nt][0] = Bs[(k8 + tg) * 136 + ncol];
                bf[nt][1] = Bs[(k8 + tg + 4) * 136 + ncol];
            }
#pragma unroll
            for (int mt = 0; mt < 4; mt++)
#pragma unroll
                for (int nt = 0; nt < 4; nt++)
                    asm volatile(
                        "mma.sync.aligned.m16n8k8.row.col.f32.tf32.tf32.f32 "
                        "{%0,%1,%2,%3}, {%4,%5,%6,%7}, {%8,%9}, {%0,%1,%2,%3};\n"
                        : "+f"(c[mt][nt][0]), "+f"(c[mt][nt][1]),
                          "+f"(c[mt][nt][2]), "+f"(c[mt][nt][3])
                        : "r"(af[mt][0]), "r"(af[mt][1]), "r"(af[mt][2]), "r"(af[mt][3]),
                          "r"(bf[nt][0]), "r"(bf[nt][1]));
        }
        __syncthreads();
    }

    // ---- epilogue ----
#pragma unroll
    for (int mt = 0; mt < 4; mt++) {
#pragma unroll
        for (int ri = 0; ri < 2; ri++) {
            int gr = rowBase + wm * 64 + mt * 16 + g + ri * 8;
#pragma unroll
            for (int nt = 0; nt < 4; nt++) {
#pragma unroll
                for (int cj = 0; cj < 2; cj++) {
                    int gc = colBase + wn * 32 + nt * 8 + 2 * tg + cj;
                    if (gc >= N) continue;
                    float v = c[mt][nt][ri * 2 + cj];
                    if (HAS_BIAS) v += bias[gc];
                    if (ACT == 1) v = gelu_exact(v);
                    if (HAS_RES) v += resid[(size_t)gr * ldr + gc];
                    Cm[(size_t)gr * ldc + gc] = v;
                }
            }
        }
    }
}

template <int ACT, bool HAS_BIAS, bool HAS_RES>
__global__ void __launch_bounds__(256, 2)
gemm_tf32_kernel(const float* __restrict__ A, int lda,
                 const float* __restrict__ Bm, int ldb,
                 const float* __restrict__ bias,
                 const float* __restrict__ resid, int ldr,
                 float* __restrict__ Cm, int ldc,
                 int M, int N, int K) {
    gemm_body<ACT, HAS_BIAS, HAS_RES>(A, lda, Bm, ldb, bias, resid, ldr, Cm, ldc, M, N, K);
}

// fused QKV: blockIdx.z selects which projection
__global__ void __launch_bounds__(256, 2)
gemm_qkv_tf32_kernel(const float* __restrict__ h,
                     const float* __restrict__ Wq, const float* __restrict__ Wk,
                     const float* __restrict__ Wv,
                     const float* __restrict__ bq, const float* __restrict__ bk,
                     const float* __restrict__ bv,
                     float* __restrict__ qo, float* __restrict__ ko,
                     float* __restrict__ vo) {
    const float* Bm; const float* bias; float* Cm;
    if (blockIdx.z == 0)      { Bm = Wq; bias = bq; Cm = qo; }
    else if (blockIdx.z == 1) { Bm = Wk; bias = bk; Cm = ko; }
    else                      { Bm = Wv; bias = bv; Cm = vo; }
    gemm_body<0, true, false>(h, C_, Bm, C_, bias, nullptr, 0, Cm, C_, MTOT, C_, C_);
}

// ---------------- attention scores (fp32 FFMA; causal, masked tiles skipped) ----
__global__ void attn_scores_kernel(const float* __restrict__ q,
                                   const float* __restrict__ k,
                                   float* __restrict__ att) {
    int z = blockIdx.z;
    int rowBase = blockIdx.y * 64;
    int colBase = blockIdx.x * 64;
    if (colBase > rowBase + 63) return;   // fully masked: never read downstream
    int b = z / H_, h = z % H_;
    int tid = threadIdx.x, tx = tid & 15, ty = tid >> 4;
    float* ab = att + (size_t)z * T_ * T_;
    const float* qb = q + (size_t)b * T_ * C_ + h * HD_;
    const float* kb = k + (size_t)b * T_ * C_ + h * HD_;
    __shared__ float Qs[HD_][65];
    __shared__ float Ks[HD_][65];
#pragma unroll
    for (int i = 0; i < 16; i++) {
        int idx = tid + i * 256;
        int m = idx >> 6, d = idx & 63;
        Qs[d][m] = qb[(size_t)(rowBase + m) * C_ + d];
        Ks[d][m] = kb[(size_t)(colBase + m) * C_ + d];
    }
    __syncthreads();
    float acc[4][4] = {};
#pragma unroll
    for (int d = 0; d < HD_; d++) {
        float a[4], bb[4];
#pragma unroll
        for (int i = 0; i < 4; i++) a[i] = Qs[d][ty * 4 + i];
#pragma unroll
        for (int j = 0; j < 4; j++) bb[j] = Ks[d][tx * 4 + j];
#pragma unroll
        for (int i = 0; i < 4; i++)
#pragma unroll
            for (int j = 0; j < 4; j++)
                acc[i][j] = fmaf(a[i], bb[j], acc[i][j]);
    }
    const float scale = 0.125f;
#pragma unroll
    for (int i = 0; i < 4; i++) {
        int gr = rowBase + ty * 4 + i;
#pragma unroll
        for (int j = 0; j < 4; j++) {
            int gc = colBase + tx * 4 + j;
            ab[(size_t)gr * T_ + gc] = acc[i][j] * scale;   // softmax ignores gc > gr
        }
    }
}

// ---------------- causal row softmax; writes zeros in tail up to 64-boundary ----
__global__ void softmax_kernel(float* __restrict__ att) {
    int row = blockIdx.x;
    int q = row % T_;
    float* p = att + (size_t)row * T_;
    int tid = threadIdx.x;
    int kend = ((q >> 6) + 1) << 6;      // region attn_av reads
    float v[4];
    float m = -INFINITY;
#pragma unroll
    for (int j = 0; j < 4; j++) {
        int cc = tid + j * 256;
        v[j] = (cc <= q) ? p[cc] : -INFINITY;
        m = fmaxf(m, v[j]);
    }
    __shared__ float red[256];
    red[tid] = m; __syncthreads();
    for (int off = 128; off > 0; off >>= 1) {
        if (tid < off) red[tid] = fmaxf(red[tid], red[tid + off]);
        __syncthreads();
    }
    m = red[0]; __syncthreads();
    float s = 0.f;
#pragma unroll
    for (int j = 0; j < 4; j++) {
        int cc = tid + j * 256;
        v[j] = (cc <= q) ? expf(v[j] - m) : 0.f;
        s += v[j];
    }
    red[tid] = s; __syncthreads();
    for (int off = 128; off > 0; off >>= 1) {
        if (tid < off) red[tid] += red[tid + off];
        __syncthreads();
    }
    float inv = 1.0f / red[0];
#pragma unroll
    for (int j = 0; j < 4; j++) {
        int cc = tid + j * 256;
        if (cc < kend) p[cc] = v[j] * inv;
    }
}

// ---------------- y = att @ V (per head, causal k-bound) ----------------
__global__ void attn_av_kernel(const float* __restrict__ att,
                               const float* __restrict__ v,
                               float* __restrict__ y) {
    int z = blockIdx.y;
    int b = z / H_, h = z % H_;
    const float* ab = att + (size_t)z * T_ * T_;
    const float* vb = v + (size_t)b * T_ * C_ + h * HD_;
    float* yb = y + (size_t)b * T_ * C_ + h * HD_;
    int rowBase = blockIdx.x * 64;
    int tid = threadIdx.x, tx = tid & 15, ty = tid >> 4;

    __shared__ float As2[16][65];
    __shared__ float Bs2[16][65];
    float acc[4][4] = {};
    int kendb = rowBase + 64;
    if (kendb > T_) kendb = T_;
    for (int kt = 0; kt < kendb; kt += 16) {
#pragma unroll
        for (int i = 0; i < 4; i++) {
            int idx = tid + i * 256;
            int m = idx >> 4, kk = idx & 15;
            As2[kk][m] = ab[(size_t)(rowBase + m) * T_ + kt + kk];
        }
#pragma unroll
        for (int i = 0; i < 4; i++) {
            int idx = tid + i * 256;
            int kk = idx >> 6, n = idx & 63;
            Bs2[kk][n] = vb[(size_t)(kt + kk) * C_ + n];
        }
        __syncthreads();
#pragma unroll
        for (int kk = 0; kk < 16; kk++) {
            float a[4], bb[4];
#pragma unroll
            for (int i = 0; i < 4; i++) a[i] = As2[kk][ty * 4 + i];
#pragma unroll
            for (int j = 0; j < 4; j++) bb[j] = Bs2[kk][tx * 4 + j];
#pragma unroll
            for (int i = 0; i < 4; i++)
#pragma unroll
                for (int j = 0; j < 4; j++)
                    acc[i][j] = fmaf(a[i], bb[j], acc[i][j]);
        }
        __syncthreads();
    }
#pragma unroll
    for (int i = 0; i < 4; i++) {
        int gr = rowBase + ty * 4 + i;
#pragma unroll
        for (int j = 0; j < 4; j++)
            yb[(size_t)gr * C_ + tx * 4 + j] = acc[i][j];
    }
}

// ---------------- per-row NLL over V ----------------
__global__ void nll_kernel(const float* __restrict__ logits,
                           const int* __restrict__ targets,
                           float* __restrict__ nll) {
    int row = blockIdx.x;
    const float* p = logits + (size_t)row * V_;
    int tid = threadIdx.x;
    __shared__ float red[256];
    float m = -INFINITY;
    for (int c = tid; c < V_; c += 256) m = fmaxf(m, p[c]);
    red[tid] = m; __syncthreads();
    for (int off = 128; off > 0; off >>= 1) {
        if (tid < off) red[tid] = fmaxf(red[tid], red[tid + off]);
        __syncthreads();
    }
    m = red[0]; __syncthreads();
    float s = 0.f;
    for (int c = tid; c < V_; c += 256) s += expf(p[c] - m);
    red[tid] = s; __syncthreads();
    for (int off = 128; off > 0; off >>= 1) {
        if (tid < off) red[tid] += red[tid + off];
        __syncthreads();
    }
    if (tid == 0) {
        float lt = p[targets[row]];
        nll[row] = -(lt - m - logf(red[0]));
    }
}

__global__ void loss_kernel(const float* __restrict__ nll, float* __restrict__ out) {
    __shared__ float red[256];
    int tid = threadIdx.x;
    float s = 0.f;
    for (int c = tid; c < MTOT; c += 256) s += nll[c];
    red[tid] = s; __syncthreads();
    for (int off = 128; off > 0; off >>= 1) {
        if (tid < off) red[tid] += red[tid + off];
        __syncthreads();
    }
    if (tid == 0) out[0] = red[0] * (1.0f / MTOT);
}

// ---------------- host launcher ----------------
extern "C" void kernel_launch(void* const* d_in, const int* in_sizes, int n_in,
                              void* d_out, int out_size) {
    const int*   idx     = (const int*)d_in[0];
    const int*   targets = (const int*)d_in[1];
    const float* tok     = (const float*)d_in[2];
    const float* pos     = (const float*)d_in[3];
    const float* ln1w    = (const float*)d_in[4];
    const float* ln1b    = (const float*)d_in[5];
    const float* ln2w    = (const float*)d_in[6];
    const float* ln2b    = (const float*)d_in[7];
    const float* Wq      = (const float*)d_in[8];
    const float* bq      = (const float*)d_in[9];
    const float* Wk      = (const float*)d_in[10];
    const float* bk      = (const float*)d_in[11];
    const float* Wv      = (const float*)d_in[12];
    const float* bv      = (const float*)d_in[13];
    const float* Wo      = (const float*)d_in[14];
    const float* bo      = (const float*)d_in[15];
    const float* W1      = (const float*)d_in[16];
    const float* b1      = (const float*)d_in[17];
    const float* W2      = (const float*)d_in[18];
    const float* b2      = (const float*)d_in[19];
    const float* lnfw    = (const float*)d_in[20];
    const float* lnfb    = (const float*)d_in[21];
    const float* headw   = (const float*)d_in[22];
    float* out = (float*)d_out;

    float *x, *h, *q, *k, *v, *y, *mlp, *att, *nllbuf, *lgs;
    cudaGetSymbolAddress((void**)&x, g_x);
    cudaGetSymbolAddress((void**)&h, g_h);
    cudaGetSymbolAddress((void**)&q, g_q);
    cudaGetSymbolAddress((void**)&k, g_k);
    cudaGetSymbolAddress((void**)&v, g_v);
    cudaGetSymbolAddress((void**)&y, g_y);
    cudaGetSymbolAddress((void**)&mlp, g_mlp);
    cudaGetSymbolAddress((void**)&att, g_att);
    cudaGetSymbolAddress((void**)&nllbuf, g_nll);
    cudaGetSymbolAddress((void**)&lgs, g_logits);

    const size_t BTV = (size_t)MTOT * V_;
    float* logits = ((size_t)out_size >= BTV) ? out : lgs;

    embed_kernel<<<MTOT, 256>>>(idx, tok, pos, x);

    dim3 gQKV(C_ / 128, MTOT / 128, 3);                 // 384 CTAs
    dim3 gC(C_ / 128, MTOT / 128);                      // 128 CTAs
    dim3 gF(FF_ / 128, MTOT / 128);                     // 512 CTAs
    dim3 gH((V_ + 127) / 128, MTOT / 128);              // 6288 CTAs

    for (int l = 0; l < L_; l++) {
        const size_t oC = (size_t)l * C_;
        const size_t oCC = (size_t)l * C_ * C_;
        const size_t oCF = (size_t)l * C_ * FF_;

        layernorm_kernel<<<MTOT, 256>>>(x, ln1w + oC, ln1b + oC, h);

        gemm_qkv_tf32_kernel<<<gQKV, 256>>>(h, Wq + oCC, Wk + oCC, Wv + oCC,
                                            bq + oC, bk + oC, bv + oC, q, k, v);

        attn_scores_kernel<<<dim3(T_ / 64, T_ / 64, B_ * H_), 256>>>(q, k, att);
        softmax_kernel<<<B_ * H_ * T_, 256>>>(att);
        attn_av_kernel<<<dim3(T_ / 64, B_ * H_), 256>>>(att, v, y);

        gemm_tf32_kernel<0, true, true><<<gC, 256>>>(y, C_, Wo + oCC, C_, bo + oC,
                                                     x, C_, x, C_, MTOT, C_, C_);

        layernorm_kernel<<<MTOT, 256>>>(x, ln2w + oC, ln2b + oC, h);

        gemm_tf32_kernel<1, true, false><<<gF, 256>>>(h, C_, W1 + oCF, FF_,
                                                      b1 + (size_t)l * FF_,
                                                      nullptr, 0, mlp, FF_, MTOT, FF_, C_);
        gemm_tf32_kernel<0, true, true><<<gC, 256>>>(mlp, FF_, W2 + oCF, C_, b2 + oC,
                                                     x, C_, x, C_, MTOT, C_, FF_);
    }

    layernorm_kernel<<<MTOT, 256>>>(x, lnfw, lnfb, h);
    gemm_tf32_kernel<0, false, false><<<gH, 256>>>(h, C_, headw, V_, nullptr,
                                                   nullptr, 0, logits, V_, MTOT, V_, C_);

    nll_kernel<<<MTOT, 256>>>(logits, targets, nllbuf);
    if ((size_t)out_size == BTV + 1) {
        loss_kernel<<<1, 256>>>(nllbuf, out + BTV);
    } else if ((size_t)out_size < BTV && out_size >= 1) {
        loss_kernel<<<1, 256>>>(nllbuf, out);
    }
}

// round 6
// speedup vs baseline: 5.0278x; 1.2865x over previous
#include <cuda_runtime.h>
#include <math.h>
#include <stdint.h>

// ---------------- problem constants ----------------
#define B_ 2
#define T_ 1024
#define C_ 1024
#define H_ 16
#define HD_ 64
#define L_ 12
#define V_ 50257
#define MTOT (B_ * T_)      // 2048 token rows
#define FF_ (4 * C_)        // 4096

// ---------------- static device scratch ----------------
__device__ float g_x[MTOT * C_];
__device__ float g_h[MTOT * C_];
__device__ float g_q[MTOT * C_];
__device__ float g_k[MTOT * C_];
__device__ float g_v[MTOT * C_];
__device__ float g_y[MTOT * C_];
__device__ float g_mlp[MTOT * FF_];
__device__ float g_att[(size_t)B_ * H_ * T_ * T_];   // 128 MB
__device__ float g_nll[MTOT];
__device__ float g_logits[(size_t)MTOT * V_];        // fallback if d_out can't hold logits

// ---------------- helpers ----------------
__device__ __forceinline__ float gelu_exact(float v) {
    return 0.5f * v * (1.0f + erff(v * 0.7071067811865476f));
}

__device__ __forceinline__ uint32_t f2tf32(float x) {
    uint32_t r;
    asm("cvt.rna.tf32.f32 %0, %1;" : "=r"(r) : "f"(x));
    return r;
}

__device__ __forceinline__ uint32_t smem_u32(const void* p) {
    return (uint32_t)__cvta_generic_to_shared(p);
}

// ---------------- embedding ----------------
__global__ void embed_kernel(const int* __restrict__ idx,
                             const float* __restrict__ tok,
                             const float* __restrict__ pos,
                             float* __restrict__ x) {
    int row = blockIdx.x;
    int t = row % T_;
    int id = idx[row];
    const float* tr = tok + (size_t)id * C_;
    const float* pr = pos + (size_t)t * C_;
    float* xr = x + (size_t)row * C_;
#pragma unroll
    for (int j = 0; j < 4; j++) {
        int c = threadIdx.x + j * 256;
        xr[c] = tr[c] + pr[c];
    }
}

// ---------------- layernorm ----------------
__global__ void layernorm_kernel(const float* __restrict__ x,
                                 const float* __restrict__ w,
                                 const float* __restrict__ b,
                                 float* __restrict__ out) {
    int row = blockIdx.x;
    int tid = threadIdx.x;
    const float* xr = x + (size_t)row * C_;
    float v[4];
    float s = 0.f;
#pragma unroll
    for (int j = 0; j < 4; j++) { v[j] = xr[tid + j * 256]; s += v[j]; }
    __shared__ float red[256];
    red[tid] = s; __syncthreads();
    for (int off = 128; off > 0; off >>= 1) {
        if (tid < off) red[tid] += red[tid + off];
        __syncthreads();
    }
    float mu = red[0] * (1.0f / C_);
    __syncthreads();
    float s2 = 0.f;
#pragma unroll
    for (int j = 0; j < 4; j++) { float d = v[j] - mu; s2 += d * d; }
    red[tid] = s2; __syncthreads();
    for (int off = 128; off > 0; off >>= 1) {
        if (tid < off) red[tid] += red[tid + off];
        __syncthreads();
    }
    float var = red[0] * (1.0f / C_);
    float rstd = rsqrtf(var + 1e-5f);
    float* orow = out + (size_t)row * C_;
#pragma unroll
    for (int j = 0; j < 4; j++) {
        int c = tid + j * 256;
        orow[c] = (v[j] - mu) * rstd * w[c] + b[c];
    }
}

// ---------------- TF32 tensor-core GEMM, cp.async 2-stage pipeline ----------------
// C[M,N] = act(A[M,K] @ B[K,N] + bias) (+resid). Block tile 128x128, BK=16.
// 128 threads = 4 warps in 2x2; warp tile 64x64; mma m16n8k8 tf32.
// Requires: M % 128 == 0, K % 16 == 0. N arbitrary.
#define AS_STRIDE 20
#define BS_STRIDE 136

template <int ACT, bool HAS_BIAS, bool HAS_RES>
__device__ __forceinline__ void gemm_body(const float* __restrict__ A, int lda,
                                          const float* __restrict__ Bm, int ldb,
                                          const float* __restrict__ bias,
                                          const float* __restrict__ resid, int ldr,
                                          float* __restrict__ Cm, int ldc,
                                          int M, int N, int K) {
    __shared__ float As[2][128 * AS_STRIDE];
    __shared__ float Bs[2][16 * BS_STRIDE];

    const int tid = threadIdx.x;
    const int lane = tid & 31, warp = tid >> 5;
    const int g = lane >> 2, tg = lane & 3;        // groupID, thread-in-group
    const int wm = warp >> 1, wn = warp & 1;       // 2x2 warp grid
    const int rowBase = blockIdx.y * 128;
    const int colBase = blockIdx.x * 128;

    float c[4][8][4];
#pragma unroll
    for (int i = 0; i < 4; i++)
#pragma unroll
        for (int j = 0; j < 8; j++)
#pragma unroll
            for (int r = 0; r < 4; r++) c[i][j][r] = 0.f;

    const bool vecB = ((ldb & 3) == 0) && (colBase + 128 <= N);

    auto loadA = [&](int s, int kt) {
#pragma unroll
        for (int i = 0; i < 4; i++) {
            int lin = tid + i * 128;
            int r = lin >> 2, c4 = lin & 3;
            uint32_t dst = smem_u32(&As[s][r * AS_STRIDE + c4 * 4]);
            const float* src = A + (size_t)(rowBase + r) * lda + kt + c4 * 4;
            asm volatile("cp.async.cg.shared.global [%0], [%1], 16;"
                         :: "r"(dst), "l"(src));
        }
    };
    auto loadB = [&](int s, int kt) {
        if (vecB) {
#pragma unroll
            for (int i = 0; i < 4; i++) {
                int lin = tid + i * 128;
                int r = lin >> 5, c4 = lin & 31;
                uint32_t dst = smem_u32(&Bs[s][r * BS_STRIDE + c4 * 4]);
                const float* src = Bm + (size_t)(kt + r) * ldb + colBase + c4 * 4;
                asm volatile("cp.async.cg.shared.global [%0], [%1], 16;"
                             :: "r"(dst), "l"(src));
            }
        } else {
#pragma unroll
            for (int i = 0; i < 16; i++) {
                int lin = tid + i * 128;
                int r = lin >> 7, cc = lin & 127;
                int gc = colBase + cc;
                uint32_t dst = smem_u32(&Bs[s][r * BS_STRIDE + cc]);
                int gcs = gc < N ? gc : (N - 1);
                const float* src = Bm + (size_t)(kt + r) * ldb + gcs;
                uint32_t ssz = (gc < N) ? 4u : 0u;
                asm volatile("cp.async.ca.shared.global [%0], [%1], 4, %2;"
                             :: "r"(dst), "l"(src), "r"(ssz));
            }
        }
    };

    loadA(0, 0);
    loadB(0, 0);
    asm volatile("cp.async.commit_group;");

    const int nkt = K >> 4;
    for (int t = 0; t < nkt; t++) {
        asm volatile("cp.async.wait_group 0;" ::: "memory");
        __syncthreads();
        if (t + 1 < nkt) {
            loadA((t + 1) & 1, (t + 1) * 16);
            loadB((t + 1) & 1, (t + 1) * 16);
            asm volatile("cp.async.commit_group;");
        }
        const int s = t & 1;
#pragma unroll
        for (int k8 = 0; k8 < 16; k8 += 8) {
            uint32_t af[4][4], bf[8][2];
#pragma unroll
            for (int mt = 0; mt < 4; mt++) {
                int mrow = wm * 64 + mt * 16 + g;
                af[mt][0] = f2tf32(As[s][mrow * AS_STRIDE + k8 + tg]);
                af[mt][1] = f2tf32(As[s][(mrow + 8) * AS_STRIDE + k8 + tg]);
                af[mt][2] = f2tf32(As[s][mrow * AS_STRIDE + k8 + tg + 4]);
                af[mt][3] = f2tf32(As[s][(mrow + 8) * AS_STRIDE + k8 + tg + 4]);
            }
#pragma unroll
            for (int nt = 0; nt < 8; nt++) {
                int ncol = wn * 64 + nt * 8 + g;
                bf[nt][0] = f2tf32(Bs[s][(k8 + tg) * BS_STRIDE + ncol]);
                bf[nt][1] = f2tf32(Bs[s][(k8 + tg + 4) * BS_STRIDE + ncol]);
            }
#pragma unroll
            for (int mt = 0; mt < 4; mt++)
#pragma unroll
                for (int nt = 0; nt < 8; nt++)
                    asm volatile(
                        "mma.sync.aligned.m16n8k8.row.col.f32.tf32.tf32.f32 "
                        "{%0,%1,%2,%3}, {%4,%5,%6,%7}, {%8,%9}, {%0,%1,%2,%3};\n"
                        : "+f"(c[mt][nt][0]), "+f"(c[mt][nt][1]),
                          "+f"(c[mt][nt][2]), "+f"(c[mt][nt][3])
                        : "r"(af[mt][0]), "r"(af[mt][1]), "r"(af[mt][2]), "r"(af[mt][3]),
                          "r"(bf[nt][0]), "r"(bf[nt][1]));
        }
    }

    // ---- epilogue ----
    const bool vecC = ((ldc & 1) == 0);
#pragma unroll
    for (int mt = 0; mt < 4; mt++) {
#pragma unroll
        for (int ri = 0; ri < 2; ri++) {
            int gr = rowBase + wm * 64 + mt * 16 + g + ri * 8;
#pragma unroll
            for (int nt = 0; nt < 8; nt++) {
                int gc = colBase + wn * 64 + nt * 8 + 2 * tg;
                if (gc >= N) continue;
                bool in1 = (gc + 1) < N;
                float v0 = c[mt][nt][ri * 2 + 0];
                float v1 = c[mt][nt][ri * 2 + 1];
                if (HAS_BIAS) { v0 += bias[gc]; if (in1) v1 += bias[gc + 1]; }
                if (ACT == 1) { v0 = gelu_exact(v0); if (in1) v1 = gelu_exact(v1); }
                if (HAS_RES) {
                    v0 += resid[(size_t)gr * ldr + gc];
                    if (in1) v1 += resid[(size_t)gr * ldr + gc + 1];
                }
                float* cp = Cm + (size_t)gr * ldc + gc;
                if (vecC && in1) {
                    *reinterpret_cast<float2*>(cp) = make_float2(v0, v1);
                } else {
                    cp[0] = v0;
                    if (in1) cp[1] = v1;
                }
            }
        }
    }
}

template <int ACT, bool HAS_BIAS, bool HAS_RES>
__global__ void __launch_bounds__(128, 2)
gemm_tf32_kernel(const float* __restrict__ A, int lda,
                 const float* __restrict__ Bm, int ldb,
                 const float* __restrict__ bias,
                 const float* __restrict__ resid, int ldr,
                 float* __restrict__ Cm, int ldc,
                 int M, int N, int K) {
    gemm_body<ACT, HAS_BIAS, HAS_RES>(A, lda, Bm, ldb, bias, resid, ldr, Cm, ldc, M, N, K);
}

// fused QKV: blockIdx.z selects which projection
__global__ void __launch_bounds__(128, 2)
gemm_qkv_tf32_kernel(const float* __restrict__ h,
                     const float* __restrict__ Wq, const float* __restrict__ Wk,
                     const float* __restrict__ Wv,
                     const float* __restrict__ bq, const float* __restrict__ bk,
                     const float* __restrict__ bv,
                     float* __restrict__ qo, float* __restrict__ ko,
                     float* __restrict__ vo) {
    const float* Bm; const float* bias; float* Cm;
    if (blockIdx.z == 0)      { Bm = Wq; bias = bq; Cm = qo; }
    else if (blockIdx.z == 1) { Bm = Wk; bias = bk; Cm = ko; }
    else                      { Bm = Wv; bias = bv; Cm = vo; }
    gemm_body<0, true, false>(h, C_, Bm, C_, bias, nullptr, 0, Cm, C_, MTOT, C_, C_);
}

// ---------------- attention scores (fp32 FFMA; causal, masked tiles skipped) ----
__global__ void attn_scores_kernel(const float* __restrict__ q,
                                   const float* __restrict__ k,
                                   float* __restrict__ att) {
    int z = blockIdx.z;
    int rowBase = blockIdx.y * 64;
    int colBase = blockIdx.x * 64;
    if (colBase > rowBase + 63) return;   // fully masked: never read downstream
    int b = z / H_, h = z % H_;
    int tid = threadIdx.x, tx = tid & 15, ty = tid >> 4;
    float* ab = att + (size_t)z * T_ * T_;
    const float* qb = q + (size_t)b * T_ * C_ + h * HD_;
    const float* kb = k + (size_t)b * T_ * C_ + h * HD_;
    __shared__ float Qs[HD_][65];
    __shared__ float Ks[HD_][65];
#pragma unroll
    for (int i = 0; i < 16; i++) {
        int idx = tid + i * 256;
        int m = idx >> 6, d = idx & 63;
        Qs[d][m] = qb[(size_t)(rowBase + m) * C_ + d];
        Ks[d][m] = kb[(size_t)(colBase + m) * C_ + d];
    }
    __syncthreads();
    float acc[4][4] = {};
#pragma unroll
    for (int d = 0; d < HD_; d++) {
        float a[4], bb[4];
#pragma unroll
        for (int i = 0; i < 4; i++) a[i] = Qs[d][ty * 4 + i];
#pragma unroll
        for (int j = 0; j < 4; j++) bb[j] = Ks[d][tx * 4 + j];
#pragma unroll
        for (int i = 0; i < 4; i++)
#pragma unroll
            for (int j = 0; j < 4; j++)
                acc[i][j] = fmaf(a[i], bb[j], acc[i][j]);
    }
    const float scale = 0.125f;
#pragma unroll
    for (int i = 0; i < 4; i++) {
        int gr = rowBase + ty * 4 + i;
#pragma unroll
        for (int j = 0; j < 4; j++) {
            int gc = colBase + tx * 4 + j;
            ab[(size_t)gr * T_ + gc] = acc[i][j] * scale;   // softmax ignores gc > gr
        }
    }
}

// ---------------- causal row softmax; writes zeros in tail up to 64-boundary ----
__global__ void softmax_kernel(float* __restrict__ att) {
    int row = blockIdx.x;
    int q = row % T_;
    float* p = att + (size_t)row * T_;
    int tid = threadIdx.x;
    int kend = ((q >> 6) + 1) << 6;      // region attn_av reads
    float v[4];
    float m = -INFINITY;
#pragma unroll
    for (int j = 0; j < 4; j++) {
        int cc = tid + j * 256;
        v[j] = (cc <= q) ? p[cc] : -INFINITY;
        m = fmaxf(m, v[j]);
    }
    __shared__ float red[256];
    red[tid] = m; __syncthreads();
    for (int off = 128; off > 0; off >>= 1) {
        if (tid < off) red[tid] = fmaxf(red[tid], red[tid + off]);
        __syncthreads();
    }
    m = red[0]; __syncthreads();
    float s = 0.f;
#pragma unroll
    for (int j = 0; j < 4; j++) {
        int cc = tid + j * 256;
        v[j] = (cc <= q) ? expf(v[j] - m) : 0.f;
        s += v[j];
    }
    red[tid] = s; __syncthreads();
    for (int off = 128; off > 0; off >>= 1) {
        if (tid < off) red[tid] += red[tid + off];
        __syncthreads();
    }
    float inv = 1.0f / red[0];
#pragma unroll
    for (int j = 0; j < 4; j++) {
        int cc = tid + j * 256;
        if (cc < kend) p[cc] = v[j] * inv;
    }
}

// ---------------- y = att @ V (per head, causal k-bound) ----------------
__global__ void attn_av_kernel(const float* __restrict__ att,
                               const float* __restrict__ v,
                               float* __restrict__ y) {
    int z = blockIdx.y;
    int b = z / H_, h = z % H_;
    const float* ab = att + (size_t)z * T_ * T_;
    const float* vb = v + (size_t)b * T_ * C_ + h * HD_;
    float* yb = y + (size_t)b * T_ * C_ + h * HD_;
    int rowBase = blockIdx.x * 64;
    int tid = threadIdx.x, tx = tid & 15, ty = tid >> 4;

    __shared__ float As2[16][65];
    __shared__ float Bs2[16][65];
    float acc[4][4] = {};
    int kendb = rowBase + 64;
    if (kendb > T_) kendb = T_;
    for (int kt = 0; kt < kendb; kt += 16) {
#pragma unroll
        for (int i = 0; i < 4; i++) {
            int idx = tid + i * 256;
            int m = idx >> 4, kk = idx & 15;
            As2[kk][m] = ab[(size_t)(rowBase + m) * T_ + kt + kk];
        }
#pragma unroll
        for (int i = 0; i < 4; i++) {
            int idx = tid + i * 256;
            int kk = idx >> 6, n = idx & 63;
            Bs2[kk][n] = vb[(size_t)(kt + kk) * C_ + n];
        }
        __syncthreads();
#pragma unroll
        for (int kk = 0; kk < 16; kk++) {
            float a[4], bb[4];
#pragma unroll
            for (int i = 0; i < 4; i++) a[i] = As2[kk][ty * 4 + i];
#pragma unroll
            for (int j = 0; j < 4; j++) bb[j] = Bs2[kk][tx * 4 + j];
#pragma unroll
            for (int i = 0; i < 4; i++)
#pragma unroll
                for (int j = 0; j < 4; j++)
                    acc[i][j] = fmaf(a[i], bb[j], acc[i][j]);
        }
        __syncthreads();
    }
#pragma unroll
    for (int i = 0; i < 4; i++) {
        int gr = rowBase + ty * 4 + i;
#pragma unroll
        for (int j = 0; j < 4; j++)
            yb[(size_t)gr * C_ + tx * 4 + j] = acc[i][j];
    }
}

// ---------------- per-row NLL over V ----------------
__global__ void nll_kernel(const float* __restrict__ logits,
                           const int* __restrict__ targets,
                           float* __restrict__ nll) {
    int row = blockIdx.x;
    const float* p = logits + (size_t)row * V_;
    int tid = threadIdx.x;
    __shared__ float red[256];
    float m = -INFINITY;
    for (int c = tid; c < V_; c += 256) m = fmaxf(m, p[c]);
    red[tid] = m; __syncthreads();
    for (int off = 128; off > 0; off >>= 1) {
        if (tid < off) red[tid] = fmaxf(red[tid], red[tid + off]);
        __syncthreads();
    }
    m = red[0]; __syncthreads();
    float s = 0.f;
    for (int c = tid; c < V_; c += 256) s += expf(p[c] - m);
    red[tid] = s; __syncthreads();
    for (int off = 128; off > 0; off >>= 1) {
        if (tid < off) red[tid] += red[tid + off];
        __syncthreads();
    }
    if (tid == 0) {
        float lt = p[targets[row]];
        nll[row] = -(lt - m - logf(red[0]));
    }
}

__global__ void loss_kernel(const float* __restrict__ nll, float* __restrict__ out) {
    __shared__ float red[256];
    int tid = threadIdx.x;
    float s = 0.f;
    for (int c = tid; c < MTOT; c += 256) s += nll[c];
    red[tid] = s; __syncthreads();
    for (int off = 128; off > 0; off >>= 1) {
        if (tid < off) red[tid] += red[tid + off];
        __syncthreads();
    }
    if (tid == 0) out[0] = red[0] * (1.0f / MTOT);
}

// ---------------- host launcher ----------------
extern "C" void kernel_launch(void* const* d_in, const int* in_sizes, int n_in,
                              void* d_out, int out_size) {
    const int*   idx     = (const int*)d_in[0];
    const int*   targets = (const int*)d_in[1];
    const float* tok     = (const float*)d_in[2];
    const float* pos     = (const float*)d_in[3];
    const float* ln1w    = (const float*)d_in[4];
    const float* ln1b    = (const float*)d_in[5];
    const float* ln2w    = (const float*)d_in[6];
    const float* ln2b    = (const float*)d_in[7];
    const float* Wq      = (const float*)d_in[8];
    const float* bq      = (const float*)d_in[9];
    const float* Wk      = (const float*)d_in[10];
    const float* bk      = (const float*)d_in[11];
    const float* Wv      = (const float*)d_in[12];
    const float* bv      = (const float*)d_in[13];
    const float* Wo      = (const float*)d_in[14];
    const float* bo      = (const float*)d_in[15];
    const float* W1      = (const float*)d_in[16];
    const float* b1      = (const float*)d_in[17];
    const float* W2      = (const float*)d_in[18];
    const float* b2      = (const float*)d_in[19];
    const float* lnfw    = (const float*)d_in[20];
    const float* lnfb    = (const float*)d_in[21];
    const float* headw   = (const float*)d_in[22];
    float* out = (float*)d_out;

    float *x, *h, *q, *k, *v, *y, *mlp, *att, *nllbuf, *lgs;
    cudaGetSymbolAddress((void**)&x, g_x);
    cudaGetSymbolAddress((void**)&h, g_h);
    cudaGetSymbolAddress((void**)&q, g_q);
    cudaGetSymbolAddress((void**)&k, g_k);
    cudaGetSymbolAddress((void**)&v, g_v);
    cudaGetSymbolAddress((void**)&y, g_y);
    cudaGetSymbolAddress((void**)&mlp, g_mlp);
    cudaGetSymbolAddress((void**)&att, g_att);
    cudaGetSymbolAddress((void**)&nllbuf, g_nll);
    cudaGetSymbolAddress((void**)&lgs, g_logits);

    const size_t BTV = (size_t)MTOT * V_;
    float* logits = ((size_t)out_size >= BTV) ? out : lgs;

    embed_kernel<<<MTOT, 256>>>(idx, tok, pos, x);

    dim3 gQKV(C_ / 128, MTOT / 128, 3);                 // 384 CTAs
    dim3 gC(C_ / 128, MTOT / 128);                      // 128 CTAs
    dim3 gF(FF_ / 128, MTOT / 128);                     // 512 CTAs
    dim3 gH((V_ + 127) / 128, MTOT / 128);              // 6288 CTAs

    for (int l = 0; l < L_; l++) {
        const size_t oC = (size_t)l * C_;
        const size_t oCC = (size_t)l * C_ * C_;
        const size_t oCF = (size_t)l * C_ * FF_;

        layernorm_kernel<<<MTOT, 256>>>(x, ln1w + oC, ln1b + oC, h);

        gemm_qkv_tf32_kernel<<<gQKV, 128>>>(h, Wq + oCC, Wk + oCC, Wv + oCC,
                                            bq + oC, bk + oC, bv + oC, q, k, v);

        attn_scores_kernel<<<dim3(T_ / 64, T_ / 64, B_ * H_), 256>>>(q, k, att);
        softmax_kernel<<<B_ * H_ * T_, 256>>>(att);
        attn_av_kernel<<<dim3(T_ / 64, B_ * H_), 256>>>(att, v, y);

        gemm_tf32_kernel<0, true, true><<<gC, 128>>>(y, C_, Wo + oCC, C_, bo + oC,
                                                     x, C_, x, C_, MTOT, C_, C_);

        layernorm_kernel<<<MTOT, 256>>>(x, ln2w + oC, ln2b + oC, h);

        gemm_tf32_kernel<1, true, false><<<gF, 128>>>(h, C_, W1 + oCF, FF_,
                                                      b1 + (size_t)l * FF_,
                                                      nullptr, 0, mlp, FF_, MTOT, FF_, C_);
        gemm_tf32_kernel<0, true, true><<<gC, 128>>>(mlp, FF_, W2 + oCF, C_, b2 + oC,
                                                     x, C_, x, C_, MTOT, C_, FF_);
    }

    layernorm_kernel<<<MTOT, 256>>>(x, lnfw, lnfb, h);
    gemm_tf32_kernel<0, false, false><<<gH, 128>>>(h, C_, headw, V_, nullptr,
                                                   nullptr, 0, logits, V_, MTOT, V_, C_);

    nll_kernel<<<MTOT, 256>>>(logits, targets, nllbuf);
    if ((size_t)out_size == BTV + 1) {
        loss_kernel<<<1, 256>>>(nllbuf, out + BTV);
    } else if ((size_t)out_size < BTV && out_size >= 1) {
        loss_kernel<<<1, 256>>>(nllbuf, out);
    }
}

// round 7
// speedup vs baseline: 5.8930x; 1.1721x over previous
#include <cuda_runtime.h>
#include <math.h>
#include <stdint.h>

// ---------------- problem constants ----------------
#define B_ 2
#define T_ 1024
#define C_ 1024
#define H_ 16
#define HD_ 64
#define L_ 12
#define V_ 50257
#define MTOT (B_ * T_)      // 2048 token rows
#define FF_ (4 * C_)        // 4096

// ---------------- static device scratch ----------------
__device__ float g_x[MTOT * C_];
__device__ float g_h[MTOT * C_];
__device__ float g_q[MTOT * C_];
__device__ float g_k[MTOT * C_];
__device__ float g_v[MTOT * C_];
__device__ float g_y[MTOT * C_];
__device__ float g_mlp[MTOT * FF_];
__device__ float g_nll[MTOT];
__device__ float g_logits[(size_t)MTOT * V_];        // fallback if d_out can't hold logits

// ---------------- helpers ----------------
__device__ __forceinline__ float gelu_exact(float v) {
    return 0.5f * v * (1.0f + erff(v * 0.7071067811865476f));
}

__device__ __forceinline__ uint32_t f2tf32(float x) {
    uint32_t r;
    asm("cvt.rna.tf32.f32 %0, %1;" : "=r"(r) : "f"(x));
    return r;
}

__device__ __forceinline__ uint32_t smem_u32(const void* p) {
    return (uint32_t)__cvta_generic_to_shared(p);
}

#define MMA_TF32(c, a0, a1, a2, a3, b0, b1)                                  \
    asm volatile(                                                            \
        "mma.sync.aligned.m16n8k8.row.col.f32.tf32.tf32.f32 "                \
        "{%0,%1,%2,%3}, {%4,%5,%6,%7}, {%8,%9}, {%0,%1,%2,%3};\n"            \
        : "+f"((c)[0]), "+f"((c)[1]), "+f"((c)[2]), "+f"((c)[3])             \
        : "r"(a0), "r"(a1), "r"(a2), "r"(a3), "r"(b0), "r"(b1))

// ---------------- embedding ----------------
__global__ void embed_kernel(const int* __restrict__ idx,
                             const float* __restrict__ tok,
                             const float* __restrict__ pos,
                             float* __restrict__ x) {
    int row = blockIdx.x;
    int t = row % T_;
    int id = idx[row];
    const float* tr = tok + (size_t)id * C_;
    const float* pr = pos + (size_t)t * C_;
    float* xr = x + (size_t)row * C_;
#pragma unroll
    for (int j = 0; j < 4; j++) {
        int c = threadIdx.x + j * 256;
        xr[c] = tr[c] + pr[c];
    }
}

// ---------------- layernorm ----------------
__global__ void layernorm_kernel(const float* __restrict__ x,
                                 const float* __restrict__ w,
                                 const float* __restrict__ b,
                                 float* __restrict__ out) {
    int row = blockIdx.x;
    int tid = threadIdx.x;
    const float* xr = x + (size_t)row * C_;
    float v[4];
    float s = 0.f;
#pragma unroll
    for (int j = 0; j < 4; j++) { v[j] = xr[tid + j * 256]; s += v[j]; }
    __shared__ float red[256];
    red[tid] = s; __syncthreads();
    for (int off = 128; off > 0; off >>= 1) {
        if (tid < off) red[tid] += red[tid + off];
        __syncthreads();
    }
    float mu = red[0] * (1.0f / C_);
    __syncthreads();
    float s2 = 0.f;
#pragma unroll
    for (int j = 0; j < 4; j++) { float d = v[j] - mu; s2 += d * d; }
    red[tid] = s2; __syncthreads();
    for (int off = 128; off > 0; off >>= 1) {
        if (tid < off) red[tid] += red[tid + off];
        __syncthreads();
    }
    float var = red[0] * (1.0f / C_);
    float rstd = rsqrtf(var + 1e-5f);
    float* orow = out + (size_t)row * C_;
#pragma unroll
    for (int j = 0; j < 4; j++) {
        int c = tid + j * 256;
        orow[c] = (v[j] - mu) * rstd * w[c] + b[c];
    }
}

// ---------------- TF32 tensor-core GEMM, cp.async 2-stage pipeline ----------------
#define AS_STRIDE 20
#define BS_STRIDE 136

template <int ACT, bool HAS_BIAS, bool HAS_RES>
__device__ __forceinline__ void gemm_body(const float* __restrict__ A, int lda,
                                          const float* __restrict__ Bm, int ldb,
                                          const float* __restrict__ bias,
                                          const float* __restrict__ resid, int ldr,
                                          float* __restrict__ Cm, int ldc,
                                          int M, int N, int K,
                                          int rowBase, int colBase) {
    __shared__ float As[2][128 * AS_STRIDE];
    __shared__ float Bs[2][16 * BS_STRIDE];

    const int tid = threadIdx.x;
    const int lane = tid & 31, warp = tid >> 5;
    const int g = lane >> 2, tg = lane & 3;
    const int wm = warp >> 1, wn = warp & 1;       // 2x2 warp grid

    float c[4][8][4];
#pragma unroll
    for (int i = 0; i < 4; i++)
#pragma unroll
        for (int j = 0; j < 8; j++)
#pragma unroll
            for (int r = 0; r < 4; r++) c[i][j][r] = 0.f;

    const bool vecB = ((ldb & 3) == 0) && (colBase + 128 <= N);

    auto loadA = [&](int s, int kt) {
#pragma unroll
        for (int i = 0; i < 4; i++) {
            int lin = tid + i * 128;
            int r = lin >> 2, c4 = lin & 3;
            uint32_t dst = smem_u32(&As[s][r * AS_STRIDE + c4 * 4]);
            const float* src = A + (size_t)(rowBase + r) * lda + kt + c4 * 4;
            asm volatile("cp.async.cg.shared.global [%0], [%1], 16;"
                         :: "r"(dst), "l"(src));
        }
    };
    auto loadB = [&](int s, int kt) {
        if (vecB) {
#pragma unroll
            for (int i = 0; i < 4; i++) {
                int lin = tid + i * 128;
                int r = lin >> 5, c4 = lin & 31;
                uint32_t dst = smem_u32(&Bs[s][r * BS_STRIDE + c4 * 4]);
                const float* src = Bm + (size_t)(kt + r) * ldb + colBase + c4 * 4;
                asm volatile("cp.async.cg.shared.global [%0], [%1], 16;"
                             :: "r"(dst), "l"(src));
            }
        } else {
#pragma unroll
            for (int i = 0; i < 16; i++) {
                int lin = tid + i * 128;
                int r = lin >> 7, cc = lin & 127;
                int gc = colBase + cc;
                uint32_t dst = smem_u32(&Bs[s][r * BS_STRIDE + cc]);
                int gcs = gc < N ? gc : (N - 1);
                const float* src = Bm + (size_t)(kt + r) * ldb + gcs;
                uint32_t ssz = (gc < N) ? 4u : 0u;
                asm volatile("cp.async.ca.shared.global [%0], [%1], 4, %2;"
                             :: "r"(dst), "l"(src), "r"(ssz));
            }
        }
    };

    loadA(0, 0);
    loadB(0, 0);
    asm volatile("cp.async.commit_group;");

    const int nkt = K >> 4;
    for (int t = 0; t < nkt; t++) {
        asm volatile("cp.async.wait_group 0;" ::: "memory");
        __syncthreads();
        if (t + 1 < nkt) {
            loadA((t + 1) & 1, (t + 1) * 16);
            loadB((t + 1) & 1, (t + 1) * 16);
            asm volatile("cp.async.commit_group;");
        }
        const int s = t & 1;
#pragma unroll
        for (int k8 = 0; k8 < 16; k8 += 8) {
            uint32_t af[4][4], bf[8][2];
#pragma unroll
            for (int mt = 0; mt < 4; mt++) {
                int mrow = wm * 64 + mt * 16 + g;
                af[mt][0] = f2tf32(As[s][mrow * AS_STRIDE + k8 + tg]);
                af[mt][1] = f2tf32(As[s][(mrow + 8) * AS_STRIDE + k8 + tg]);
                af[mt][2] = f2tf32(As[s][mrow * AS_STRIDE + k8 + tg + 4]);
                af[mt][3] = f2tf32(As[s][(mrow + 8) * AS_STRIDE + k8 + tg + 4]);
            }
#pragma unroll
            for (int nt = 0; nt < 8; nt++) {
                int ncol = wn * 64 + nt * 8 + g;
                bf[nt][0] = f2tf32(Bs[s][(k8 + tg) * BS_STRIDE + ncol]);
                bf[nt][1] = f2tf32(Bs[s][(k8 + tg + 4) * BS_STRIDE + ncol]);
            }
#pragma unroll
            for (int mt = 0; mt < 4; mt++)
#pragma unroll
                for (int nt = 0; nt < 8; nt++)
                    MMA_TF32(c[mt][nt], af[mt][0], af[mt][1], af[mt][2], af[mt][3],
                             bf[nt][0], bf[nt][1]);
        }
    }

    // ---- epilogue ----
    const bool vecC = ((ldc & 1) == 0);
#pragma unroll
    for (int mt = 0; mt < 4; mt++) {
#pragma unroll
        for (int ri = 0; ri < 2; ri++) {
            int gr = rowBase + wm * 64 + mt * 16 + g + ri * 8;
#pragma unroll
            for (int nt = 0; nt < 8; nt++) {
                int gc = colBase + wn * 64 + nt * 8 + 2 * tg;
                if (gc >= N) continue;
                bool in1 = (gc + 1) < N;
                float v0 = c[mt][nt][ri * 2 + 0];
                float v1 = c[mt][nt][ri * 2 + 1];
                if (HAS_BIAS) { v0 += bias[gc]; if (in1) v1 += bias[gc + 1]; }
                if (ACT == 1) { v0 = gelu_exact(v0); if (in1) v1 = gelu_exact(v1); }
                if (HAS_RES) {
                    v0 += resid[(size_t)gr * ldr + gc];
                    if (in1) v1 += resid[(size_t)gr * ldr + gc + 1];
                }
                float* cp = Cm + (size_t)gr * ldc + gc;
                if (vecC && in1) {
                    *reinterpret_cast<float2*>(cp) = make_float2(v0, v1);
                } else {
                    cp[0] = v0;
                    if (in1) cp[1] = v1;
                }
            }
        }
    }
}

template <int ACT, bool HAS_BIAS, bool HAS_RES, bool SWAP>
__global__ void __launch_bounds__(128, 2)
gemm_tf32_kernel(const float* __restrict__ A, int lda,
                 const float* __restrict__ Bm, int ldb,
                 const float* __restrict__ bias,
                 const float* __restrict__ resid, int ldr,
                 float* __restrict__ Cm, int ldc,
                 int M, int N, int K) {
    int rowBase = (SWAP ? blockIdx.x : blockIdx.y) * 128;
    int colBase = (SWAP ? blockIdx.y : blockIdx.x) * 128;
    gemm_body<ACT, HAS_BIAS, HAS_RES>(A, lda, Bm, ldb, bias, resid, ldr,
                                      Cm, ldc, M, N, K, rowBase, colBase);
}

// fused QKV: blockIdx.z selects which projection
__global__ void __launch_bounds__(128, 2)
gemm_qkv_tf32_kernel(const float* __restrict__ h,
                     const float* __restrict__ Wq, const float* __restrict__ Wk,
                     const float* __restrict__ Wv,
                     const float* __restrict__ bq, const float* __restrict__ bk,
                     const float* __restrict__ bv,
                     float* __restrict__ qo, float* __restrict__ ko,
                     float* __restrict__ vo) {
    const float* Bm; const float* bias; float* Cm;
    if (blockIdx.z == 0)      { Bm = Wq; bias = bq; Cm = qo; }
    else if (blockIdx.z == 1) { Bm = Wk; bias = bk; Cm = ko; }
    else                      { Bm = Wv; bias = bv; Cm = vo; }
    gemm_body<0, true, false>(h, C_, Bm, C_, bias, nullptr, 0, Cm, C_, MTOT, C_, C_,
                              blockIdx.y * 128, blockIdx.x * 128);
}

// ---------------- fused flash attention ----------------
// Per CTA: one (bh, 64-row q-tile). 128 threads = 4 warps.
// S = Q.K^T via TF32 MMA (warp w owns rows w*16..w*16+15), online softmax in fp32,
// O += P.V in fp32 FFMA (thread grid 16x8, 4 rows x 8 cols each).
#define FPAD 65
#define VPAD 68
#define FLASH_SMEM ((64 * FPAD /*Q*/ + 2 * 64 * FPAD /*K*/ + 2 * 64 * VPAD /*V*/ + \
                     64 * FPAD /*P*/ + 192) * 4)

__global__ void __launch_bounds__(128, 2)
flash_attn_kernel(const float* __restrict__ q, const float* __restrict__ k,
                  const float* __restrict__ v, float* __restrict__ y) {
    extern __shared__ float sm[];
    float* Qs = sm;                       // [m][d]   64 x FPAD
    float* KsB = Qs + 64 * FPAD;          // [d][n]   2 x 64 x FPAD
    float* VsB = KsB + 2 * 64 * FPAD;     // [n][d]   2 x 64 x VPAD
    float* Ps = VsB + 2 * 64 * VPAD;      // [m][n]   64 x FPAD
    float* m_s = Ps + 64 * FPAD;          // 64
    float* l_s = m_s + 64;                // 64
    float* al_s = l_s + 64;               // 64

    const int tid = threadIdx.x;
    const int lane = tid & 31, warp = tid >> 5;
    const int g = lane >> 2, tg = lane & 3;
    const int z = blockIdx.y;
    const int b = z >> 4, h = z & 15;
    const int qt = (T_ / 64 - 1) - blockIdx.x;   // heavy CTAs first
    const int rowBase = qt * 64;

    const float* qb = q + (size_t)b * T_ * C_ + h * HD_;
    const float* kb = k + (size_t)b * T_ * C_ + h * HD_;
    const float* vb = v + (size_t)b * T_ * C_ + h * HD_;
    float* yb = y + (size_t)b * T_ * C_ + h * HD_;

    // Q tile load with 1/sqrt(HD)=0.125 folded in (exact pow2 scale)
#pragma unroll
    for (int i = 0; i < 32; i++) {
        int lin = tid + i * 128;
        int mm = lin >> 6, d = lin & 63;
        Qs[mm * FPAD + d] = qb[(size_t)(rowBase + mm) * C_ + d] * 0.125f;
    }
    if (tid < 64) { m_s[tid] = -INFINITY; l_s[tid] = 0.f; }

    auto loadKV = [&](int s, int kt) {
        const float* kbt = kb + (size_t)kt * 64 * C_;
        const float* vbt = vb + (size_t)kt * 64 * C_;
        float* Kd = KsB + s * 64 * FPAD;
        float* Vd = VsB + s * 64 * VPAD;
#pragma unroll
        for (int i = 0; i < 32; i++) {          // K transposed scatter, 4B each
            int lin = tid + i * 128;
            int n = lin >> 6, d = lin & 63;
            uint32_t dk = smem_u32(&Kd[d * FPAD + n]);
            asm volatile("cp.async.ca.shared.global [%0], [%1], 4;"
                         :: "r"(dk), "l"(kbt + (size_t)n * C_ + d));
        }
#pragma unroll
        for (int i = 0; i < 8; i++) {           // V natural, 16B chunks
            int lin = tid + i * 128;
            int n = lin >> 4, d4 = lin & 15;
            uint32_t dv = smem_u32(&Vd[n * VPAD + d4 * 4]);
            asm volatile("cp.async.cg.shared.global [%0], [%1], 16;"
                         :: "r"(dv), "l"(vbt + (size_t)n * C_ + d4 * 4));
        }
    };

    loadKV(0, 0);
    asm volatile("cp.async.commit_group;");

    const int tyy = tid >> 3, tx8 = tid & 7;
    float O[4][8];
#pragma unroll
    for (int i = 0; i < 4; i++)
#pragma unroll
        for (int j = 0; j < 8; j++) O[i][j] = 0.f;

    const int r0 = warp * 16 + g, r1 = r0 + 8;   // local S rows owned (MMA layout)

    for (int kt = 0; kt <= qt; kt++) {
        const int s = kt & 1;
        asm volatile("cp.async.wait_group 0;" ::: "memory");
        __syncthreads();
        if (kt < qt) loadKV(s ^ 1, kt + 1);
        asm volatile("cp.async.commit_group;");

        // ---- S = Q.K^T (TF32 MMA) ----
        const float* Kp = KsB + s * 64 * FPAD;
        float sf[8][4];
#pragma unroll
        for (int nt = 0; nt < 8; nt++)
#pragma unroll
            for (int r = 0; r < 4; r++) sf[nt][r] = 0.f;
#pragma unroll
        for (int k8 = 0; k8 < 64; k8 += 8) {
            uint32_t a0 = f2tf32(Qs[r0 * FPAD + k8 + tg]);
            uint32_t a1 = f2tf32(Qs[r1 * FPAD + k8 + tg]);
            uint32_t a2 = f2tf32(Qs[r0 * FPAD + k8 + tg + 4]);
            uint32_t a3 = f2tf32(Qs[r1 * FPAD + k8 + tg + 4]);
#pragma unroll
            for (int nt = 0; nt < 8; nt++) {
                uint32_t b0 = f2tf32(Kp[(k8 + tg) * FPAD + nt * 8 + g]);
                uint32_t b1 = f2tf32(Kp[(k8 + tg + 4) * FPAD + nt * 8 + g]);
                MMA_TF32(sf[nt], a0, a1, a2, a3, b0, b1);
            }
        }

        // ---- causal mask (diag tile only) ----
        if (kt == qt) {
            int gr0 = rowBase + r0, gr1 = rowBase + r1;
            int cb = kt * 64;
#pragma unroll
            for (int nt = 0; nt < 8; nt++) {
                int c0 = cb + nt * 8 + 2 * tg, c1 = c0 + 1;
                if (c0 > gr0) sf[nt][0] = -1e30f;
                if (c1 > gr0) sf[nt][1] = -1e30f;
                if (c0 > gr1) sf[nt][2] = -1e30f;
                if (c1 > gr1) sf[nt][3] = -1e30f;
            }
        }

        // ---- online softmax update ----
        float mx0 = -INFINITY, mx1 = -INFINITY;
#pragma unroll
        for (int nt = 0; nt < 8; nt++) {
            mx0 = fmaxf(mx0, fmaxf(sf[nt][0], sf[nt][1]));
            mx1 = fmaxf(mx1, fmaxf(sf[nt][2], sf[nt][3]));
        }
        mx0 = fmaxf(mx0, __shfl_xor_sync(0xFFFFFFFF, mx0, 1));
        mx0 = fmaxf(mx0, __shfl_xor_sync(0xFFFFFFFF, mx0, 2));
        mx1 = fmaxf(mx1, __shfl_xor_sync(0xFFFFFFFF, mx1, 1));
        mx1 = fmaxf(mx1, __shfl_xor_sync(0xFFFFFFFF, mx1, 2));

        float mo0 = m_s[r0], mo1 = m_s[r1];
        float mn0 = fmaxf(mo0, mx0), mn1 = fmaxf(mo1, mx1);
        float a0s = __expf(mo0 - mn0), a1s = __expf(mo1 - mn1);

        float rs0 = 0.f, rs1 = 0.f;
#pragma unroll
        for (int nt = 0; nt < 8; nt++) {
            sf[nt][0] = __expf(sf[nt][0] - mn0);
            sf[nt][1] = __expf(sf[nt][1] - mn0);
            sf[nt][2] = __expf(sf[nt][2] - mn1);
            sf[nt][3] = __expf(sf[nt][3] - mn1);
            rs0 += sf[nt][0] + sf[nt][1];
            rs1 += sf[nt][2] + sf[nt][3];
        }
        rs0 += __shfl_xor_sync(0xFFFFFFFF, rs0, 1);
        rs0 += __shfl_xor_sync(0xFFFFFFFF, rs0, 2);
        rs1 += __shfl_xor_sync(0xFFFFFFFF, rs1, 1);
        rs1 += __shfl_xor_sync(0xFFFFFFFF, rs1, 2);

        if (tg == 0) {
            m_s[r0] = mn0; m_s[r1] = mn1;
            l_s[r0] = l_s[r0] * a0s + rs0;
            l_s[r1] = l_s[r1] * a1s + rs1;
            al_s[r0] = a0s; al_s[r1] = a1s;
        }
        // P to smem
#pragma unroll
        for (int nt = 0; nt < 8; nt++) {
            int cc = nt * 8 + 2 * tg;
            Ps[r0 * FPAD + cc] = sf[nt][0];
            Ps[r0 * FPAD + cc + 1] = sf[nt][1];
            Ps[r1 * FPAD + cc] = sf[nt][2];
            Ps[r1 * FPAD + cc + 1] = sf[nt][3];
        }
        __syncthreads();

        // ---- O = O*alpha + P.V (fp32) ----
        float al[4];
#pragma unroll
        for (int i = 0; i < 4; i++) al[i] = al_s[tyy * 4 + i];
#pragma unroll
        for (int i = 0; i < 4; i++)
#pragma unroll
            for (int j = 0; j < 8; j++) O[i][j] *= al[i];

        const float* Vp = VsB + s * 64 * VPAD;
#pragma unroll 8
        for (int kk = 0; kk < 64; kk++) {
            float a[4], bb[8];
#pragma unroll
            for (int i = 0; i < 4; i++) a[i] = Ps[(tyy * 4 + i) * FPAD + kk];
#pragma unroll
            for (int j = 0; j < 8; j++) bb[j] = Vp[kk * VPAD + tx8 + 8 * j];
#pragma unroll
            for (int i = 0; i < 4; i++)
#pragma unroll
                for (int j = 0; j < 8; j++) O[i][j] = fmaf(a[i], bb[j], O[i][j]);
        }
    }

    // ---- epilogue: y = O / l ----
#pragma unroll
    for (int i = 0; i < 4; i++) {
        int r = tyy * 4 + i;
        float inv = 1.0f / l_s[r];
        float* yr = yb + (size_t)(rowBase + r) * C_;
#pragma unroll
        for (int j = 0; j < 8; j++) yr[tx8 + 8 * j] = O[i][j] * inv;
    }
}

// ---------------- per-row NLL over V (single-pass online) ----------------
__global__ void nll_kernel(const float* __restrict__ logits,
                           const int* __restrict__ targets,
                           float* __restrict__ nll) {
    int row = blockIdx.x;
    const float* p = logits + (size_t)row * V_;
    int tid = threadIdx.x;
    float m = -INFINITY, s = 0.f;
    for (int c = tid; c < V_; c += 256) {
        float v = p[c];
        if (v <= m) {
            s += expf(v - m);
        } else {
            s = s * expf(m - v) + 1.0f;
            m = v;
        }
    }
    __shared__ float rm[256], rs[256];
    rm[tid] = m; rs[tid] = s; __syncthreads();
    for (int off = 128; off > 0; off >>= 1) {
        if (tid < off) {
            float m1 = rm[tid], s1 = rs[tid];
            float m2 = rm[tid + off], s2 = rs[tid + off];
            float M = fmaxf(m1, m2);
            rm[tid] = M;
            rs[tid] = s1 * expf(m1 - M) + s2 * expf(m2 - M);
        }
        __syncthreads();
    }
    if (tid == 0) {
        float lt = p[targets[row]];
        nll[row] = -(lt - rm[0] - logf(rs[0]));
    }
}

__global__ void loss_kernel(const float* __restrict__ nll, float* __restrict__ out) {
    __shared__ float red[256];
    int tid = threadIdx.x;
    float s = 0.f;
    for (int c = tid; c < MTOT; c += 256) s += nll[c];
    red[tid] = s; __syncthreads();
    for (int off = 128; off > 0; off >>= 1) {
        if (tid < off) red[tid] += red[tid + off];
        __syncthreads();
    }
    if (tid == 0) out[0] = red[0] * (1.0f / MTOT);
}

// ---------------- host launcher ----------------
extern "C" void kernel_launch(void* const* d_in, const int* in_sizes, int n_in,
                              void* d_out, int out_size) {
    const int*   idx     = (const int*)d_in[0];
    const int*   targets = (const int*)d_in[1];
    const float* tok     = (const float*)d_in[2];
    const float* pos     = (const float*)d_in[3];
    const float* ln1w    = (const float*)d_in[4];
    const float* ln1b    = (const float*)d_in[5];
    const float* ln2w    = (const float*)d_in[6];
    const float* ln2b    = (const float*)d_in[7];
    const float* Wq      = (const float*)d_in[8];
    const float* bq      = (const float*)d_in[9];
    const float* Wk      = (const float*)d_in[10];
    const float* bk      = (const float*)d_in[11];
    const float* Wv      = (const float*)d_in[12];
    const float* bv      = (const float*)d_in[13];
    const float* Wo      = (const float*)d_in[14];
    const float* bo      = (const float*)d_in[15];
    const float* W1      = (const float*)d_in[16];
    const float* b1      = (const float*)d_in[17];
    const float* W2      = (const float*)d_in[18];
    const float* b2      = (const float*)d_in[19];
    const float* lnfw    = (const float*)d_in[20];
    const float* lnfb    = (const float*)d_in[21];
    const float* headw   = (const float*)d_in[22];
    float* out = (float*)d_out;

    float *x, *h, *q, *k, *v, *y, *mlp, *nllbuf, *lgs;
    cudaGetSymbolAddress((void**)&x, g_x);
    cudaGetSymbolAddress((void**)&h, g_h);
    cudaGetSymbolAddress((void**)&q, g_q);
    cudaGetSymbolAddress((void**)&k, g_k);
    cudaGetSymbolAddress((void**)&v, g_v);
    cudaGetSymbolAddress((void**)&y, g_y);
    cudaGetSymbolAddress((void**)&mlp, g_mlp);
    cudaGetSymbolAddress((void**)&nllbuf, g_nll);
    cudaGetSymbolAddress((void**)&lgs, g_logits);

    cudaFuncSetAttribute(flash_attn_kernel,
                         cudaFuncAttributeMaxDynamicSharedMemorySize, FLASH_SMEM);

    const size_t BTV = (size_t)MTOT * V_;
    float* logits = ((size_t)out_size >= BTV) ? out : lgs;

    embed_kernel<<<MTOT, 256>>>(idx, tok, pos, x);

    dim3 gQKV(C_ / 128, MTOT / 128, 3);                 // 384 CTAs
    dim3 gC(C_ / 128, MTOT / 128);                      // 128 CTAs
    dim3 gF(FF_ / 128, MTOT / 128);                     // 512 CTAs
    dim3 gHsw(MTOT / 128, (V_ + 127) / 128);            // head GEMM, row-fastest (L2 B reuse)
    dim3 gFA(T_ / 64, B_ * H_);                         // flash attention: 512 CTAs

    for (int l = 0; l < L_; l++) {
        const size_t oC = (size_t)l * C_;
        const size_t oCC = (size_t)l * C_ * C_;
        const size_t oCF = (size_t)l * C_ * FF_;

        layernorm_kernel<<<MTOT, 256>>>(x, ln1w + oC, ln1b + oC, h);

        gemm_qkv_tf32_kernel<<<gQKV, 128>>>(h, Wq + oCC, Wk + oCC, Wv + oCC,
                                            bq + oC, bk + oC, bv + oC, q, k, v);

        flash_attn_kernel<<<gFA, 128, FLASH_SMEM>>>(q, k, v, y);

        gemm_tf32_kernel<0, true, true, false><<<gC, 128>>>(y, C_, Wo + oCC, C_, bo + oC,
                                                            x, C_, x, C_, MTOT, C_, C_);

        layernorm_kernel<<<MTOT, 256>>>(x, ln2w + oC, ln2b + oC, h);

        gemm_tf32_kernel<1, true, false, false><<<gF, 128>>>(h, C_, W1 + oCF, FF_,
                                                             b1 + (size_t)l * FF_,
                                                             nullptr, 0, mlp, FF_,
                                                             MTOT, FF_, C_);
        gemm_tf32_kernel<0, true, true, false><<<gC, 128>>>(mlp, FF_, W2 + oCF, C_, b2 + oC,
                                                            x, C_, x, C_, MTOT, C_, FF_);
    }

    layernorm_kernel<<<MTOT, 256>>>(x, lnfw, lnfb, h);
    gemm_tf32_kernel<0, false, false, true><<<gHsw, 128>>>(h, C_, headw, V_, nullptr,
                                                           nullptr, 0, logits, V_,
                                                           MTOT, V_, C_);

    nll_kernel<<<MTOT, 256>>>(logits, targets, nllbuf);
    if ((size_t)out_size == BTV + 1) {
        loss_kernel<<<1, 256>>>(nllbuf, out + BTV);
    } else if ((size_t)out_size < BTV && out_size >= 1) {
        loss_kernel<<<1, 256>>>(nllbuf, out);
    }
}

// round 8
// speedup vs baseline: 7.0752x; 1.2006x over previous
#include <cuda_runtime.h>
#include <math.h>
#include <stdint.h>

// ---------------- problem constants ----------------
#define B_ 2
#define T_ 1024
#define C_ 1024
#define H_ 16
#define HD_ 64
#define L_ 12
#define V_ 50257
#define MTOT (B_ * T_)      // 2048 token rows
#define FF_ (4 * C_)        // 4096

// ---------------- static device scratch ----------------
__device__ float g_x[MTOT * C_];
__device__ float g_h[MTOT * C_];
__device__ float g_q[MTOT * C_];
__device__ float g_k[MTOT * C_];
__device__ float g_v[MTOT * C_];
__device__ float g_y[MTOT * C_];
__device__ float g_mlp[MTOT * FF_];
__device__ float g_nll[MTOT];
__device__ float g_logits[(size_t)MTOT * V_];        // fallback if d_out can't hold logits

// ---------------- helpers ----------------
__device__ __forceinline__ float gelu_exact(float v) {
    return 0.5f * v * (1.0f + erff(v * 0.7071067811865476f));
}

__device__ __forceinline__ uint32_t f2tf32(float x) {
    uint32_t r;
    asm("cvt.rna.tf32.f32 %0, %1;" : "=r"(r) : "f"(x));
    return r;
}

__device__ __forceinline__ uint32_t smem_u32(const void* p) {
    return (uint32_t)__cvta_generic_to_shared(p);
}

#define MMA_TF32(c, a0, a1, a2, a3, b0, b1)                                  \
    asm volatile(                                                            \
        "mma.sync.aligned.m16n8k8.row.col.f32.tf32.tf32.f32 "                \
        "{%0,%1,%2,%3}, {%4,%5,%6,%7}, {%8,%9}, {%0,%1,%2,%3};\n"            \
        : "+f"((c)[0]), "+f"((c)[1]), "+f"((c)[2]), "+f"((c)[3])             \
        : "r"(a0), "r"(a1), "r"(a2), "r"(a3), "r"(b0), "r"(b1))

#define CP_ASYNC16(dst, src)                                                 \
    asm volatile("cp.async.cg.shared.global [%0], [%1], 16;"                 \
                 :: "r"(dst), "l"(src))
#define CP_COMMIT() asm volatile("cp.async.commit_group;")
#define CP_WAIT(n)  asm volatile("cp.async.wait_group %0;" :: "n"(n) : "memory")

// ---------------- embedding ----------------
__global__ void embed_kernel(const int* __restrict__ idx,
                             const float* __restrict__ tok,
                             const float* __restrict__ pos,
                             float* __restrict__ x) {
    int row = blockIdx.x;
    int t = row % T_;
    int id = idx[row];
    const float* tr = tok + (size_t)id * C_;
    const float* pr = pos + (size_t)t * C_;
    float* xr = x + (size_t)row * C_;
#pragma unroll
    for (int j = 0; j < 4; j++) {
        int c = threadIdx.x + j * 256;
        xr[c] = tr[c] + pr[c];
    }
}

// ---------------- layernorm ----------------
__global__ void layernorm_kernel(const float* __restrict__ x,
                                 const float* __restrict__ w,
                                 const float* __restrict__ b,
                                 float* __restrict__ out) {
    int row = blockIdx.x;
    int tid = threadIdx.x;
    const float* xr = x + (size_t)row * C_;
    float v[4];
    float s = 0.f;
#pragma unroll
    for (int j = 0; j < 4; j++) { v[j] = xr[tid + j * 256]; s += v[j]; }
    __shared__ float red[256];
    red[tid] = s; __syncthreads();
    for (int off = 128; off > 0; off >>= 1) {
        if (tid < off) red[tid] += red[tid + off];
        __syncthreads();
    }
    float mu = red[0] * (1.0f / C_);
    __syncthreads();
    float s2 = 0.f;
#pragma unroll
    for (int j = 0; j < 4; j++) { float d = v[j] - mu; s2 += d * d; }
    red[tid] = s2; __syncthreads();
    for (int off = 128; off > 0; off >>= 1) {
        if (tid < off) red[tid] += red[tid + off];
        __syncthreads();
    }
    float var = red[0] * (1.0f / C_);
    float rstd = rsqrtf(var + 1e-5f);
    float* orow = out + (size_t)row * C_;
#pragma unroll
    for (int j = 0; j < 4; j++) {
        int c = tid + j * 256;
        orow[c] = (v[j] - mu) * rstd * w[c] + b[c];
    }
}

// ---------------- TF32 tensor-core GEMM, cp.async 4-stage pipeline ----------------
#define AS_STRIDE 20
#define BS_STRIDE 136
#define GSTAGES 4
#define AS_ELEMS (128 * AS_STRIDE)
#define BS_ELEMS (16 * BS_STRIDE)
#define GEMM_SMEM ((AS_ELEMS + BS_ELEMS) * GSTAGES * 4)

template <int ACT, bool HAS_BIAS, bool HAS_RES>
__device__ __forceinline__ void gemm_body(const float* __restrict__ A, int lda,
                                          const float* __restrict__ Bm, int ldb,
                                          const float* __restrict__ bias,
                                          const float* __restrict__ resid, int ldr,
                                          float* __restrict__ Cm, int ldc,
                                          int M, int N, int K,
                                          int rowBase, int colBase) {
    extern __shared__ float dsm[];
    float* As = dsm;                           // [GSTAGES][AS_ELEMS]
    float* Bs = dsm + GSTAGES * AS_ELEMS;      // [GSTAGES][BS_ELEMS]

    const int tid = threadIdx.x;
    const int lane = tid & 31, warp = tid >> 5;
    const int g = lane >> 2, tg = lane & 3;
    const int wm = warp >> 1, wn = warp & 1;   // 2x2 warp grid

    float c[4][8][4];
#pragma unroll
    for (int i = 0; i < 4; i++)
#pragma unroll
        for (int j = 0; j < 8; j++)
#pragma unroll
            for (int r = 0; r < 4; r++) c[i][j][r] = 0.f;

    const bool vecB = ((ldb & 3) == 0) && (colBase + 128 <= N);

    auto loadA = [&](int s, int kt) {
        float* Ad = As + s * AS_ELEMS;
#pragma unroll
        for (int i = 0; i < 4; i++) {
            int lin = tid + i * 128;
            int r = lin >> 2, c4 = lin & 3;
            uint32_t dst = smem_u32(&Ad[r * AS_STRIDE + c4 * 4]);
            const float* src = A + (size_t)(rowBase + r) * lda + kt + c4 * 4;
            CP_ASYNC16(dst, src);
        }
    };
    auto loadB = [&](int s, int kt) {
        float* Bd = Bs + s * BS_ELEMS;
        if (vecB) {
#pragma unroll
            for (int i = 0; i < 4; i++) {
                int lin = tid + i * 128;
                int r = lin >> 5, c4 = lin & 31;
                uint32_t dst = smem_u32(&Bd[r * BS_STRIDE + c4 * 4]);
                const float* src = Bm + (size_t)(kt + r) * ldb + colBase + c4 * 4;
                CP_ASYNC16(dst, src);
            }
        } else {
#pragma unroll
            for (int i = 0; i < 16; i++) {
                int lin = tid + i * 128;
                int r = lin >> 7, cc = lin & 127;
                int gc = colBase + cc;
                uint32_t dst = smem_u32(&Bd[r * BS_STRIDE + cc]);
                int gcs = gc < N ? gc : (N - 1);
                const float* src = Bm + (size_t)(kt + r) * ldb + gcs;
                uint32_t ssz = (gc < N) ? 4u : 0u;
                asm volatile("cp.async.ca.shared.global [%0], [%1], 4, %2;"
                             :: "r"(dst), "l"(src), "r"(ssz));
            }
        }
    };

    const int nkt = K >> 4;                    // >= 64 for all our GEMMs
#pragma unroll
    for (int s = 0; s < GSTAGES - 1; s++) {    // prologue: 3 tiles in flight
        loadA(s, s * 16);
        loadB(s, s * 16);
        CP_COMMIT();
    }

    for (int t = 0; t < nkt; t++) {
        CP_WAIT(GSTAGES - 2);
        __syncthreads();
        int ld = t + GSTAGES - 1;
        if (ld < nkt) {
            loadA(ld & 3, ld * 16);
            loadB(ld & 3, ld * 16);
        }
        CP_COMMIT();

        const int s = t & 3;
        const float* Ap = As + s * AS_ELEMS;
        const float* Bp = Bs + s * BS_ELEMS;
#pragma unroll
        for (int k8 = 0; k8 < 16; k8 += 8) {
            uint32_t af[4][4], bf[8][2];
#pragma unroll
            for (int mt = 0; mt < 4; mt++) {
                int mrow = wm * 64 + mt * 16 + g;
                af[mt][0] = f2tf32(Ap[mrow * AS_STRIDE + k8 + tg]);
                af[mt][1] = f2tf32(Ap[(mrow + 8) * AS_STRIDE + k8 + tg]);
                af[mt][2] = f2tf32(Ap[mrow * AS_STRIDE + k8 + tg + 4]);
                af[mt][3] = f2tf32(Ap[(mrow + 8) * AS_STRIDE + k8 + tg + 4]);
            }
#pragma unroll
            for (int nt = 0; nt < 8; nt++) {
                int ncol = wn * 64 + nt * 8 + g;
                bf[nt][0] = f2tf32(Bp[(k8 + tg) * BS_STRIDE + ncol]);
                bf[nt][1] = f2tf32(Bp[(k8 + tg + 4) * BS_STRIDE + ncol]);
            }
#pragma unroll
            for (int mt = 0; mt < 4; mt++)
#pragma unroll
                for (int nt = 0; nt < 8; nt++)
                    MMA_TF32(c[mt][nt], af[mt][0], af[mt][1], af[mt][2], af[mt][3],
                             bf[nt][0], bf[nt][1]);
        }
    }

    // ---- epilogue ----
    const bool vecC = ((ldc & 1) == 0);
#pragma unroll
    for (int mt = 0; mt < 4; mt++) {
#pragma unroll
        for (int ri = 0; ri < 2; ri++) {
            int gr = rowBase + wm * 64 + mt * 16 + g + ri * 8;
#pragma unroll
            for (int nt = 0; nt < 8; nt++) {
                int gc = colBase + wn * 64 + nt * 8 + 2 * tg;
                if (gc >= N) continue;
                bool in1 = (gc + 1) < N;
                float v0 = c[mt][nt][ri * 2 + 0];
                float v1 = c[mt][nt][ri * 2 + 1];
                if (HAS_BIAS) { v0 += bias[gc]; if (in1) v1 += bias[gc + 1]; }
                if (ACT == 1) { v0 = gelu_exact(v0); if (in1) v1 = gelu_exact(v1); }
                if (HAS_RES) {
                    v0 += resid[(size_t)gr * ldr + gc];
                    if (in1) v1 += resid[(size_t)gr * ldr + gc + 1];
                }
                float* cp = Cm + (size_t)gr * ldc + gc;
                if (vecC && in1) {
                    *reinterpret_cast<float2*>(cp) = make_float2(v0, v1);
                } else {
                    cp[0] = v0;
                    if (in1) cp[1] = v1;
                }
            }
        }
    }
}

template <int ACT, bool HAS_BIAS, bool HAS_RES, bool SWAP>
__global__ void __launch_bounds__(128, 2)
gemm_tf32_kernel(const float* __restrict__ A, int lda,
                 const float* __restrict__ Bm, int ldb,
                 const float* __restrict__ bias,
                 const float* __restrict__ resid, int ldr,
                 float* __restrict__ Cm, int ldc,
                 int M, int N, int K) {
    int rowBase = (SWAP ? blockIdx.x : blockIdx.y) * 128;
    int colBase = (SWAP ? blockIdx.y : blockIdx.x) * 128;
    gemm_body<ACT, HAS_BIAS, HAS_RES>(A, lda, Bm, ldb, bias, resid, ldr,
                                      Cm, ldc, M, N, K, rowBase, colBase);
}

// fused QKV: blockIdx.z selects which projection
__global__ void __launch_bounds__(128, 2)
gemm_qkv_tf32_kernel(const float* __restrict__ h,
                     const float* __restrict__ Wq, const float* __restrict__ Wk,
                     const float* __restrict__ Wv,
                     const float* __restrict__ bq, const float* __restrict__ bk,
                     const float* __restrict__ bv,
                     float* __restrict__ qo, float* __restrict__ ko,
                     float* __restrict__ vo) {
    const float* Bm; const float* bias; float* Cm;
    if (blockIdx.z == 0)      { Bm = Wq; bias = bq; Cm = qo; }
    else if (blockIdx.z == 1) { Bm = Wk; bias = bk; Cm = ko; }
    else                      { Bm = Wv; bias = bv; Cm = vo; }
    gemm_body<0, true, false>(h, C_, Bm, C_, bias, nullptr, 0, Cm, C_, MTOT, C_, C_,
                              blockIdx.y * 128, blockIdx.x * 128);
}

// ---------------- fused flash attention (S and PV both on TF32 MMA) ----------------
// Per CTA: one (bh, 64-row q-tile). 128 threads = 4 warps; warp w owns rows w*16..w*16+15.
// All smem natural-layout, 16B cp.async, pads chosen for conflict-free fragment reads:
//   Q[64][QP=68], K[2][64][KP=68], V[2][64][VP=72], P[64][PP=68]
#define QP 68
#define KP 68
#define VP 72
#define PP 68
#define FLASH_SMEM ((64 * QP + 2 * 64 * KP + 2 * 64 * VP + 64 * PP) * 4)

__global__ void __launch_bounds__(128, 2)
flash_attn_kernel(const float* __restrict__ q, const float* __restrict__ k,
                  const float* __restrict__ v, float* __restrict__ y) {
    extern __shared__ float sm[];
    float* Qs = sm;                       // [m][d]
    float* Ks = Qs + 64 * QP;             // 2 x [n][d]
    float* Vs = Ks + 2 * 64 * KP;         // 2 x [n][d]
    float* Ps = Vs + 2 * 64 * VP;         // [m][n]

    const int tid = threadIdx.x;
    const int lane = tid & 31, warp = tid >> 5;
    const int g = lane >> 2, tg = lane & 3;
    const int z = blockIdx.y;
    const int b = z >> 4, h = z & 15;
    const int qt = (T_ / 64 - 1) - blockIdx.x;   // heavy CTAs first
    const int rowBase = qt * 64;

    const float* qb = q + (size_t)b * T_ * C_ + h * HD_;
    const float* kb = k + (size_t)b * T_ * C_ + h * HD_;
    const float* vb = v + (size_t)b * T_ * C_ + h * HD_;
    float* yb = y + (size_t)b * T_ * C_ + h * HD_;

    auto loadKV = [&](int s, int kt) {
        const float* kbt = kb + (size_t)kt * 64 * C_;
        const float* vbt = vb + (size_t)kt * 64 * C_;
        float* Kd = Ks + s * 64 * KP;
        float* Vd = Vs + s * 64 * VP;
#pragma unroll
        for (int i = 0; i < 8; i++) {
            int lin = tid + i * 128;
            int n = lin >> 4, d4 = lin & 15;
            CP_ASYNC16(smem_u32(&Kd[n * KP + d4 * 4]), kbt + (size_t)n * C_ + d4 * 4);
        }
#pragma unroll
        for (int i = 0; i < 8; i++) {
            int lin = tid + i * 128;
            int n = lin >> 4, d4 = lin & 15;
            CP_ASYNC16(smem_u32(&Vd[n * VP + d4 * 4]), vbt + (size_t)n * C_ + d4 * 4);
        }
    };

    // Q tile (once) + first KV stage in one group
#pragma unroll
    for (int i = 0; i < 8; i++) {
        int lin = tid + i * 128;
        int mm = lin >> 4, d4 = lin & 15;
        CP_ASYNC16(smem_u32(&Qs[mm * QP + d4 * 4]), qb + (size_t)(rowBase + mm) * C_ + d4 * 4);
    }
    loadKV(0, 0);
    CP_COMMIT();

    const int r0 = warp * 16 + g, r1 = r0 + 8;   // rows owned (S and O share layout)
    float m0 = -INFINITY, m1 = -INFINITY, l0 = 0.f, l1 = 0.f;
    float of[8][4];
#pragma unroll
    for (int nt = 0; nt < 8; nt++)
#pragma unroll
        for (int r = 0; r < 4; r++) of[nt][r] = 0.f;

    for (int kt = 0; kt <= qt; kt++) {
        const int s = kt & 1;
        CP_WAIT(0);
        __syncthreads();
        if (kt < qt) loadKV(s ^ 1, kt + 1);
        CP_COMMIT();

        // ---- S = Q.K^T (TF32 MMA), K natural [n][d] read K-major ----
        const float* Kp = Ks + s * 64 * KP;
        float sf[8][4];
#pragma unroll
        for (int nt = 0; nt < 8; nt++)
#pragma unroll
            for (int r = 0; r < 4; r++) sf[nt][r] = 0.f;
#pragma unroll
        for (int k8 = 0; k8 < 64; k8 += 8) {
            uint32_t a0 = f2tf32(Qs[r0 * QP + k8 + tg]);
            uint32_t a1 = f2tf32(Qs[r1 * QP + k8 + tg]);
            uint32_t a2 = f2tf32(Qs[r0 * QP + k8 + tg + 4]);
            uint32_t a3 = f2tf32(Qs[r1 * QP + k8 + tg + 4]);
#pragma unroll
            for (int nt = 0; nt < 8; nt++) {
                int ncol = nt * 8 + g;
                uint32_t b0 = f2tf32(Kp[ncol * KP + k8 + tg]);
                uint32_t b1 = f2tf32(Kp[ncol * KP + k8 + tg + 4]);
                MMA_TF32(sf[nt], a0, a1, a2, a3, b0, b1);
            }
        }
#pragma unroll
        for (int nt = 0; nt < 8; nt++)
#pragma unroll
            for (int r = 0; r < 4; r++) sf[nt][r] *= 0.125f;   // 1/sqrt(HD)

        // ---- causal mask (diag tile only) ----
        if (kt == qt) {
            int gr0 = rowBase + r0, gr1 = rowBase + r1;
            int cb = kt * 64;
#pragma unroll
            for (int nt = 0; nt < 8; nt++) {
                int c0 = cb + nt * 8 + 2 * tg, c1 = c0 + 1;
                if (c0 > gr0) sf[nt][0] = -1e30f;
                if (c1 > gr0) sf[nt][1] = -1e30f;
                if (c0 > gr1) sf[nt][2] = -1e30f;
                if (c1 > gr1) sf[nt][3] = -1e30f;
            }
        }

        // ---- online softmax (registers only; quad-shuffle reductions) ----
        float mx0 = -INFINITY, mx1 = -INFINITY;
#pragma unroll
        for (int nt = 0; nt < 8; nt++) {
            mx0 = fmaxf(mx0, fmaxf(sf[nt][0], sf[nt][1]));
            mx1 = fmaxf(mx1, fmaxf(sf[nt][2], sf[nt][3]));
        }
        mx0 = fmaxf(mx0, __shfl_xor_sync(0xFFFFFFFF, mx0, 1));
        mx0 = fmaxf(mx0, __shfl_xor_sync(0xFFFFFFFF, mx0, 2));
        mx1 = fmaxf(mx1, __shfl_xor_sync(0xFFFFFFFF, mx1, 1));
        mx1 = fmaxf(mx1, __shfl_xor_sync(0xFFFFFFFF, mx1, 2));

        float mn0 = fmaxf(m0, mx0), mn1 = fmaxf(m1, mx1);
        float a0s = __expf(m0 - mn0), a1s = __expf(m1 - mn1);

        float rs0 = 0.f, rs1 = 0.f;
#pragma unroll
        for (int nt = 0; nt < 8; nt++) {
            sf[nt][0] = __expf(sf[nt][0] - mn0);
            sf[nt][1] = __expf(sf[nt][1] - mn0);
            sf[nt][2] = __expf(sf[nt][2] - mn1);
            sf[nt][3] = __expf(sf[nt][3] - mn1);
            rs0 += sf[nt][0] + sf[nt][1];
            rs1 += sf[nt][2] + sf[nt][3];
        }
        rs0 += __shfl_xor_sync(0xFFFFFFFF, rs0, 1);
        rs0 += __shfl_xor_sync(0xFFFFFFFF, rs0, 2);
        rs1 += __shfl_xor_sync(0xFFFFFFFF, rs1, 1);
        rs1 += __shfl_xor_sync(0xFFFFFFFF, rs1, 2);

        m0 = mn0; m1 = mn1;
        l0 = l0 * a0s + rs0;
        l1 = l1 * a1s + rs1;

        // ---- P to smem (only this warp's rows; warp-local reuse) ----
#pragma unroll
        for (int nt = 0; nt < 8; nt++) {
            int cc = nt * 8 + 2 * tg;
            *reinterpret_cast<float2*>(&Ps[r0 * PP + cc]) = make_float2(sf[nt][0], sf[nt][1]);
            *reinterpret_cast<float2*>(&Ps[r1 * PP + cc]) = make_float2(sf[nt][2], sf[nt][3]);
        }
        __syncwarp();

        // ---- O = O*alpha + P.V (TF32 MMA), V natural [n][d] ----
#pragma unroll
        for (int nt = 0; nt < 8; nt++) {
            of[nt][0] *= a0s; of[nt][1] *= a0s;
            of[nt][2] *= a1s; of[nt][3] *= a1s;
        }
        const float* Vp = Vs + s * 64 * VP;
#pragma unroll
        for (int k8 = 0; k8 < 64; k8 += 8) {
            uint32_t a0 = f2tf32(Ps[r0 * PP + k8 + tg]);
            uint32_t a1 = f2tf32(Ps[r1 * PP + k8 + tg]);
            uint32_t a2 = f2tf32(Ps[r0 * PP + k8 + tg + 4]);
            uint32_t a3 = f2tf32(Ps[r1 * PP + k8 + tg + 4]);
#pragma unroll
            for (int nt = 0; nt < 8; nt++) {
                int ncol = nt * 8 + g;
                uint32_t b0 = f2tf32(Vp[(k8 + tg) * VP + ncol]);
                uint32_t b1 = f2tf32(Vp[(k8 + tg + 4) * VP + ncol]);
                MMA_TF32(of[nt], a0, a1, a2, a3, b0, b1);
            }
        }
    }

    // ---- epilogue: y = O / l (fragment layout direct to gmem) ----
    float inv0 = 1.0f / l0, inv1 = 1.0f / l1;
    float* yr0 = yb + (size_t)(rowBase + r0) * C_;
    float* yr1 = yb + (size_t)(rowBase + r1) * C_;
#pragma unroll
    for (int nt = 0; nt < 8; nt++) {
        int cc = nt * 8 + 2 * tg;
        *reinterpret_cast<float2*>(yr0 + cc) = make_float2(of[nt][0] * inv0, of[nt][1] * inv0);
        *reinterpret_cast<float2*>(yr1 + cc) = make_float2(of[nt][2] * inv1, of[nt][3] * inv1);
    }
}

// ---------------- per-row NLL over V (single-pass online) ----------------
__global__ void nll_kernel(const float* __restrict__ logits,
                           const int* __restrict__ targets,
                           float* __restrict__ nll) {
    int row = blockIdx.x;
    const float* p = logits + (size_t)row * V_;
    int tid = threadIdx.x;
    float m = -INFINITY, s = 0.f;
    for (int c = tid; c < V_; c += 256) {
        float v = p[c];
        if (v <= m) {
            s += expf(v - m);
        } else {
            s = s * expf(m - v) + 1.0f;
            m = v;
        }
    }
    __shared__ float rm[256], rs[256];
    rm[tid] = m; rs[tid] = s; __syncthreads();
    for (int off = 128; off > 0; off >>= 1) {
        if (tid < off) {
            float m1 = rm[tid], s1 = rs[tid];
            float m2 = rm[tid + off], s2 = rs[tid + off];
            float M = fmaxf(m1, m2);
            rm[tid] = M;
            rs[tid] = s1 * expf(m1 - M) + s2 * expf(m2 - M);
        }
        __syncthreads();
    }
    if (tid == 0) {
        float lt = p[targets[row]];
        nll[row] = -(lt - rm[0] - logf(rs[0]));
    }
}

__global__ void loss_kernel(const float* __restrict__ nll, float* __restrict__ out) {
    __shared__ float red[256];
    int tid = threadIdx.x;
    float s = 0.f;
    for (int c = tid; c < MTOT; c += 256) s += nll[c];
    red[tid] = s; __syncthreads();
    for (int off = 128; off > 0; off >>= 1) {
        if (tid < off) red[tid] += red[tid + off];
        __syncthreads();
    }
    if (tid == 0) out[0] = red[0] * (1.0f / MTOT);
}

// ---------------- host launcher ----------------
extern "C" void kernel_launch(void* const* d_in, const int* in_sizes, int n_in,
                              void* d_out, int out_size) {
    const int*   idx     = (const int*)d_in[0];
    const int*   targets = (const int*)d_in[1];
    const float* tok     = (const float*)d_in[2];
    const float* pos     = (const float*)d_in[3];
    const float* ln1w    = (const float*)d_in[4];
    const float* ln1b    = (const float*)d_in[5];
    const float* ln2w    = (const float*)d_in[6];
    const float* ln2b    = (const float*)d_in[7];
    const float* Wq      = (const float*)d_in[8];
    const float* bq      = (const float*)d_in[9];
    const float* Wk      = (const float*)d_in[10];
    const float* bk      = (const float*)d_in[11];
    const float* Wv      = (const float*)d_in[12];
    const float* bv      = (const float*)d_in[13];
    const float* Wo      = (const float*)d_in[14];
    const float* bo      = (const float*)d_in[15];
    const float* W1      = (const float*)d_in[16];
    const float* b1      = (const float*)d_in[17];
    const float* W2      = (const float*)d_in[18];
    const float* b2      = (const float*)d_in[19];
    const float* lnfw    = (const float*)d_in[20];
    const float* lnfb    = (const float*)d_in[21];
    const float* headw   = (const float*)d_in[22];
    float* out = (float*)d_out;

    float *x, *h, *q, *k, *v, *y, *mlp, *nllbuf, *lgs;
    cudaGetSymbolAddress((void**)&x, g_x);
    cudaGetSymbolAddress((void**)&h, g_h);
    cudaGetSymbolAddress((void**)&q, g_q);
    cudaGetSymbolAddress((void**)&k, g_k);
    cudaGetSymbolAddress((void**)&v, g_v);
    cudaGetSymbolAddress((void**)&y, g_y);
    cudaGetSymbolAddress((void**)&mlp, g_mlp);
    cudaGetSymbolAddress((void**)&nllbuf, g_nll);
    cudaGetSymbolAddress((void**)&lgs, g_logits);

    cudaFuncSetAttribute(flash_attn_kernel,
                         cudaFuncAttributeMaxDynamicSharedMemorySize, FLASH_SMEM);
    cudaFuncSetAttribute(gemm_qkv_tf32_kernel,
                         cudaFuncAttributeMaxDynamicSharedMemorySize, GEMM_SMEM);
    cudaFuncSetAttribute(gemm_tf32_kernel<0, true, true, false>,
                         cudaFuncAttributeMaxDynamicSharedMemorySize, GEMM_SMEM);
    cudaFuncSetAttribute(gemm_tf32_kernel<1, true, false, false>,
                         cudaFuncAttributeMaxDynamicSharedMemorySize, GEMM_SMEM);
    cudaFuncSetAttribute(gemm_tf32_kernel<0, false, false, true>,
                         cudaFuncAttributeMaxDynamicSharedMemorySize, GEMM_SMEM);

    const size_t BTV = (size_t)MTOT * V_;
    float* logits = ((size_t)out_size >= BTV) ? out : lgs;

    embed_kernel<<<MTOT, 256>>>(idx, tok, pos, x);

    dim3 gQKV(C_ / 128, MTOT / 128, 3);                 // 384 CTAs
    dim3 gC(C_ / 128, MTOT / 128);                      // 128 CTAs
    dim3 gF(FF_ / 128, MTOT / 128);                     // 512 CTAs
    dim3 gHsw(MTOT / 128, (V_ + 127) / 128);            // head GEMM, row-fastest (L2 B reuse)
    dim3 gFA(T_ / 64, B_ * H_);                         // flash attention: 512 CTAs

    for (int l = 0; l < L_; l++) {
        const size_t oC = (size_t)l * C_;
        const size_t oCC = (size_t)l * C_ * C_;
        const size_t oCF = (size_t)l * C_ * FF_;

        layernorm_kernel<<<MTOT, 256>>>(x, ln1w + oC, ln1b + oC, h);

        gemm_qkv_tf32_kernel<<<gQKV, 128, GEMM_SMEM>>>(h, Wq + oCC, Wk + oCC, Wv + oCC,
                                                       bq + oC, bk + oC, bv + oC, q, k, v);

        flash_attn_kernel<<<gFA, 128, FLASH_SMEM>>>(q, k, v, y);

        gemm_tf32_kernel<0, true, true, false><<<gC, 128, GEMM_SMEM>>>(
            y, C_, Wo + oCC, C_, bo + oC, x, C_, x, C_, MTOT, C_, C_);

        layernorm_kernel<<<MTOT, 256>>>(x, ln2w + oC, ln2b + oC, h);

        gemm_tf32_kernel<1, true, false, false><<<gF, 128, GEMM_SMEM>>>(
            h, C_, W1 + oCF, FF_, b1 + (size_t)l * FF_, nullptr, 0, mlp, FF_, MTOT, FF_, C_);
        gemm_tf32_kernel<0, true, true, false><<<gC, 128, GEMM_SMEM>>>(
            mlp, FF_, W2 + oCF, C_, b2 + oC, x, C_, x, C_, MTOT, C_, FF_);
    }

    layernorm_kernel<<<MTOT, 256>>>(x, lnfw, lnfb, h);
    gemm_tf32_kernel<0, false, false, true><<<gHsw, 128, GEMM_SMEM>>>(
        h, C_, headw, V_, nullptr, nullptr, 0, logits, V_, MTOT, V_, C_);

    nll_kernel<<<MTOT, 256>>>(logits, targets, nllbuf);
    if ((size_t)out_size == BTV + 1) {
        loss_kernel<<<1, 256>>>(nllbuf, out + BTV);
    } else if ((size_t)out_size < BTV && out_size >= 1) {
        loss_kernel<<<1, 256>>>(nllbuf, out);
    }
}